// round 1
// baseline (speedup 1.0000x reference)
#include <cuda_runtime.h>
#include <math.h>

#define MROWS 4096   // B * S
#define DM    1024
#define DH    64
#define NH    16
#define DMLP  4096
#define SEQ   2048
#define BATCH 2

// ---------------- scratch (static device globals; no runtime alloc) ----------
__device__ float g_xln [MROWS * DM];        // 16 MB
__device__ float g_qkv [MROWS * 3 * DM];    // 48 MB  layout [row][{Q,K,V} x (n*64+h)]
__device__ float g_ctx [MROWS * DM];        // 16 MB
__device__ float g_mid [MROWS * DM];        // 16 MB
__device__ float g_y   [MROWS * DM];        // 16 MB
__device__ float g_h   [MROWS * DMLP];      // 64 MB
__device__ float g_wqkv[DM * 3 * DM];       // 12 MB packed [e][3072]
__device__ float g_bqkv[3 * DM];

// ---------------- layernorm: one block per row -------------------------------
__global__ __launch_bounds__(256) void ln_kernel(const float* __restrict__ x,
                                                 const float* __restrict__ w,
                                                 const float* __restrict__ bb,
                                                 float* __restrict__ out)
{
    int row = blockIdx.x;
    int t = threadIdx.x;
    const float* xr = x + (size_t)row * DM;
    float4 xv = reinterpret_cast<const float4*>(xr)[t];
    float s  = xv.x + xv.y + xv.z + xv.w;
    float sq = xv.x*xv.x + xv.y*xv.y + xv.z*xv.z + xv.w*xv.w;
    #pragma unroll
    for (int off = 16; off > 0; off >>= 1) {
        s  += __shfl_xor_sync(0xffffffffu, s,  off);
        sq += __shfl_xor_sync(0xffffffffu, sq, off);
    }
    __shared__ float ss[8], sk[8];
    __shared__ float smean, sinv;
    if ((t & 31) == 0) { ss[t >> 5] = s; sk[t >> 5] = sq; }
    __syncthreads();
    if (t == 0) {
        float S = 0.f, Q = 0.f;
        #pragma unroll
        for (int i = 0; i < 8; i++) { S += ss[i]; Q += sk[i]; }
        float mean = S * (1.0f / DM);
        float var  = Q * (1.0f / DM) - mean * mean;
        smean = mean;
        sinv  = rsqrtf(var + 1e-5f);
    }
    __syncthreads();
    float mean = smean, inv = sinv;
    float4 wv = reinterpret_cast<const float4*>(w)[t];
    float4 bv = reinterpret_cast<const float4*>(bb)[t];
    float4 ov;
    ov.x = (xv.x - mean) * inv * wv.x + bv.x;
    ov.y = (xv.y - mean) * inv * wv.y + bv.y;
    ov.z = (xv.z - mean) * inv * wv.z + bv.z;
    ov.w = (xv.w - mean) * inv * wv.w + bv.w;
    reinterpret_cast<float4*>(out + (size_t)row * DM)[t] = ov;
}

// ---------------- pack QKV weights into one [1024 x 3072] matrix -------------
__global__ void pack_qkv_kernel(const float* __restrict__ Wq, const float* __restrict__ Wk,
                                const float* __restrict__ Wv, const float* __restrict__ Bq,
                                const float* __restrict__ Bk, const float* __restrict__ Bv)
{
    int idx = blockIdx.x * 256 + threadIdx.x;
    if (idx < DM * 3 * DM) {
        int e   = idx / (3 * DM);
        int cc  = idx % (3 * DM);
        int sel = cc / DM;
        int col = cc % DM;
        const float* W = (sel == 0) ? Wq : (sel == 1) ? Wk : Wv;
        // W_*: (NH, DM, DH) -> [n][e][h]
        g_wqkv[idx] = W[(size_t)(col >> 6) * DM * DH + (size_t)e * DH + (col & 63)];
    }
    if (idx < 3 * DM) {
        int sel = idx / DM, col = idx % DM;
        const float* Bp = (sel == 0) ? Bq : (sel == 1) ? Bk : Bv;
        g_bqkv[idx] = Bp[col];   // (NH, DH) flat == n*64+h
    }
}

// ---------------- SIMT sgemm 128x128x16, 8x8 per thread ----------------------
// C[M,N] = A[M,K] * B[K,N]   (all row-major, dims multiples of tile sizes)
// mode 0: +bias     mode 1: +bias, exact GELU     mode 2: +bias, +add (residual)
#define BM 128
#define BN 128
#define BK 16

__global__ __launch_bounds__(256) void sgemm_kernel(
    const float* __restrict__ A, const float* __restrict__ Bm,
    float* __restrict__ C, int M, int N, int K,
    const float* __restrict__ bias, const float* __restrict__ add, int mode)
{
    __shared__ float As[BK][BM + 4];
    __shared__ float Bs[BK][BN + 4];
    int t  = threadIdx.x;
    int tx = t & 15, ty = t >> 4;
    int m0 = blockIdx.y * BM, n0 = blockIdx.x * BN;

    float c[8][8];
    #pragma unroll
    for (int i = 0; i < 8; i++)
        #pragma unroll
        for (int j = 0; j < 8; j++) c[i][j] = 0.f;

    for (int k0 = 0; k0 < K; k0 += BK) {
        #pragma unroll
        for (int u = 0; u < 2; u++) {
            int f = t * 2 + u;               // float4 index 0..511
            int ar = f >> 2, ac4 = f & 3;    // A tile: 128 rows x 4 float4
            float4 av = *reinterpret_cast<const float4*>(A + (size_t)(m0 + ar) * K + k0 + ac4 * 4);
            As[ac4 * 4 + 0][ar] = av.x;
            As[ac4 * 4 + 1][ar] = av.y;
            As[ac4 * 4 + 2][ar] = av.z;
            As[ac4 * 4 + 3][ar] = av.w;
            int br = f >> 5, bc4 = f & 31;   // B tile: 16 rows x 32 float4
            *reinterpret_cast<float4*>(&Bs[br][bc4 * 4]) =
                *reinterpret_cast<const float4*>(Bm + (size_t)(k0 + br) * N + n0 + bc4 * 4);
        }
        __syncthreads();
        #pragma unroll
        for (int k = 0; k < BK; k++) {
            float a[8], b[8];
            #pragma unroll
            for (int i = 0; i < 8; i++) a[i] = As[k][ty + 16 * i];
            #pragma unroll
            for (int j = 0; j < 8; j++) b[j] = Bs[k][tx + 16 * j];
            #pragma unroll
            for (int i = 0; i < 8; i++)
                #pragma unroll
                for (int j = 0; j < 8; j++) c[i][j] += a[i] * b[j];
        }
        __syncthreads();
    }

    #pragma unroll
    for (int i = 0; i < 8; i++) {
        int gm = m0 + ty + 16 * i;
        #pragma unroll
        for (int j = 0; j < 8; j++) {
            int gn = n0 + tx + 16 * j;
            float v = c[i][j] + bias[gn];
            if (mode == 1) {
                v = 0.5f * v * (1.0f + erff(v * 0.70710678118654752f));
            } else if (mode == 2) {
                v += add[(size_t)gm * N + gn];
            }
            C[(size_t)gm * N + gn] = v;
        }
    }
}

// ---------------- flash attention with EPS mask (full softmax over all k) ----
// Q tile 64 rows, K tile 32 cols, head dim 64. Per thread: 4 rows x {2 score
// cols, 4 out dims}. 16 lanes (same ty) cooperate per row via shfl_xor 1,2,4,8.
#define QT 64
#define KT 32
#define DHP (DH + 4)
#define KTP (KT + 4)

__global__ __launch_bounds__(256) void flash_kernel(const float* __restrict__ qkv,
                                                    float* __restrict__ ctx)
{
    __shared__ float Qs[QT][DHP];
    __shared__ float Ks[KT][DHP];
    __shared__ float Vs[KT][DHP];
    __shared__ float Ps[QT][KTP];

    int t  = threadIdx.x;
    int tx = t & 15, ty = t >> 4;
    int qt = blockIdx.x;
    int n  = blockIdx.y & (NH - 1);
    int b  = blockIdx.y >> 4;
    int q0 = qt * QT;
    const float* base = qkv + (size_t)b * SEQ * (3 * DM);

    // load + pre-scale Q by 1/sqrt(64)
    for (int f = t; f < QT * 16; f += 256) {
        int r = f >> 4, c4 = f & 15;
        float4 v = *reinterpret_cast<const float4*>(base + (size_t)(q0 + r) * (3 * DM) + n * 64 + c4 * 4);
        v.x *= 0.125f; v.y *= 0.125f; v.z *= 0.125f; v.w *= 0.125f;
        *reinterpret_cast<float4*>(&Qs[r][c4 * 4]) = v;
    }

    float m[4], l[4], o[4][4];
    #pragma unroll
    for (int i = 0; i < 4; i++) {
        m[i] = -INFINITY; l[i] = 0.f;
        #pragma unroll
        for (int j = 0; j < 4; j++) o[i][j] = 0.f;
    }

    for (int k0 = 0; k0 < SEQ; k0 += KT) {   // EPS-mask quirk: ALL tiles contribute
        __syncthreads();
        for (int f = t; f < KT * 16; f += 256) {
            int r = f >> 4, c4 = f & 15;
            const float* g = base + (size_t)(k0 + r) * (3 * DM) + DM + n * 64 + c4 * 4;
            *reinterpret_cast<float4*>(&Ks[r][c4 * 4]) = *reinterpret_cast<const float4*>(g);
            *reinterpret_cast<float4*>(&Vs[r][c4 * 4]) = *reinterpret_cast<const float4*>(g + DM);
        }
        __syncthreads();

        float acc[4][2];
        #pragma unroll
        for (int i = 0; i < 4; i++) { acc[i][0] = 0.f; acc[i][1] = 0.f; }
        #pragma unroll
        for (int kk = 0; kk < DH; kk++) {
            float kv0 = Ks[tx][kk];
            float kv1 = Ks[tx + 16][kk];
            #pragma unroll
            for (int i = 0; i < 4; i++) {
                float qv = Qs[ty * 4 + i][kk];
                acc[i][0] += qv * kv0;
                acc[i][1] += qv * kv1;
            }
        }

        #pragma unroll
        for (int i = 0; i < 4; i++) {
            int qg = q0 + ty * 4 + i;
            float s0 = (qg < k0 + tx)      ? 1e-10f : acc[i][0];
            float s1 = (qg < k0 + tx + 16) ? 1e-10f : acc[i][1];
            float mt = fmaxf(s0, s1);
            #pragma unroll
            for (int msk = 1; msk < 16; msk <<= 1)
                mt = fmaxf(mt, __shfl_xor_sync(0xffffffffu, mt, msk));
            float mn = fmaxf(m[i], mt);
            float p0 = __expf(s0 - mn);
            float p1 = __expf(s1 - mn);
            float lt = p0 + p1;
            #pragma unroll
            for (int msk = 1; msk < 16; msk <<= 1)
                lt += __shfl_xor_sync(0xffffffffu, lt, msk);
            float corr = __expf(m[i] - mn);
            l[i] = l[i] * corr + lt;
            #pragma unroll
            for (int j = 0; j < 4; j++) o[i][j] *= corr;
            m[i] = mn;
            Ps[ty * 4 + i][tx]      = p0;
            Ps[ty * 4 + i][tx + 16] = p1;
        }
        __syncthreads();

        #pragma unroll
        for (int k = 0; k < KT; k++) {
            float p[4], vv[4];
            #pragma unroll
            for (int i = 0; i < 4; i++) p[i] = Ps[ty * 4 + i][k];
            #pragma unroll
            for (int j = 0; j < 4; j++) vv[j] = Vs[k][tx + 16 * j];
            #pragma unroll
            for (int i = 0; i < 4; i++)
                #pragma unroll
                for (int j = 0; j < 4; j++) o[i][j] += p[i] * vv[j];
        }
    }

    int brow = b * SEQ + q0;
    #pragma unroll
    for (int i = 0; i < 4; i++) {
        float invl = 1.0f / l[i];
        #pragma unroll
        for (int j = 0; j < 4; j++)
            ctx[(size_t)(brow + ty * 4 + i) * DM + n * 64 + tx + 16 * j] = o[i][j] * invl;
    }
}

// ---------------- launch -----------------------------------------------------
extern "C" void kernel_launch(void* const* d_in, const int* in_sizes, int n_in,
                              void* d_out, int out_size)
{
    const float* residual   = (const float*)d_in[0];
    const float* W_key      = (const float*)d_in[1];
    const float* W_query    = (const float*)d_in[2];
    const float* W_values   = (const float*)d_in[3];
    const float* W_attn_out = (const float*)d_in[4];
    const float* B_key      = (const float*)d_in[5];
    const float* B_query    = (const float*)d_in[6];
    const float* B_values   = (const float*)d_in[7];
    const float* B_attn_out = (const float*)d_in[8];
    const float* ln1_w      = (const float*)d_in[9];
    const float* ln1_b      = (const float*)d_in[10];
    const float* ln2_w      = (const float*)d_in[11];
    const float* ln2_b      = (const float*)d_in[12];
    const float* W_mlp_in   = (const float*)d_in[13];
    const float* W_mlp_out  = (const float*)d_in[14];
    const float* B_mlp_in   = (const float*)d_in[15];
    const float* B_mlp_out  = (const float*)d_in[16];
    float* out = (float*)d_out;

    float *xln, *qkvp, *ctxp, *midp, *yp, *hp, *wqkvp, *bqkvp;
    cudaGetSymbolAddress((void**)&xln,   g_xln);
    cudaGetSymbolAddress((void**)&qkvp,  g_qkv);
    cudaGetSymbolAddress((void**)&ctxp,  g_ctx);
    cudaGetSymbolAddress((void**)&midp,  g_mid);
    cudaGetSymbolAddress((void**)&yp,    g_y);
    cudaGetSymbolAddress((void**)&hp,    g_h);
    cudaGetSymbolAddress((void**)&wqkvp, g_wqkv);
    cudaGetSymbolAddress((void**)&bqkvp, g_bqkv);

    // 1. LN1
    ln_kernel<<<MROWS, 256>>>(residual, ln1_w, ln1_b, xln);
    // 2. pack QKV weights/biases
    pack_qkv_kernel<<<(DM * 3 * DM + 255) / 256, 256>>>(W_query, W_key, W_values,
                                                        B_query, B_key, B_values);
    // 3. QKV projection: [4096,1024] x [1024,3072]
    sgemm_kernel<<<dim3(3 * DM / BN, MROWS / BM), 256>>>(
        xln, wqkvp, qkvp, MROWS, 3 * DM, DM, bqkvp, nullptr, 0);
    // 4. attention (EPS-masked full softmax)
    flash_kernel<<<dim3(SEQ / QT, BATCH * NH), 256>>>(qkvp, ctxp);
    // 5. attn out projection + residual -> mid
    sgemm_kernel<<<dim3(DM / BN, MROWS / BM), 256>>>(
        ctxp, W_attn_out, midp, MROWS, DM, DM, B_attn_out, residual, 2);
    // 6. LN2
    ln_kernel<<<MROWS, 256>>>(midp, ln2_w, ln2_b, yp);
    // 7. MLP in + exact GELU
    sgemm_kernel<<<dim3(DMLP / BN, MROWS / BM), 256>>>(
        yp, W_mlp_in, hp, MROWS, DMLP, DM, B_mlp_in, nullptr, 1);
    // 8. MLP out + residual -> output
    sgemm_kernel<<<dim3(DM / BN, MROWS / BM), 256>>>(
        hp, W_mlp_out, out, MROWS, DM, DMLP, B_mlp_out, midp, 2);
}

// round 2
// speedup vs baseline: 1.1369x; 1.1369x over previous
#include <cuda_runtime.h>
#include <math.h>

#define MROWS 4096   // B * S
#define DM    1024
#define DH    64
#define NH    16
#define DMLP  4096
#define SEQ   2048
#define BATCH 2

// ---------------- scratch (static device globals; no runtime alloc) ----------
__device__ float g_xln [MROWS * DM];
__device__ float g_qkv [MROWS * 3 * DM];    // [row][{Q,K,V} x (n*64+h)]
__device__ float g_ctx [MROWS * DM];
__device__ float g_mid [MROWS * DM];
__device__ float g_y   [MROWS * DM];
__device__ float g_h   [MROWS * DMLP];
__device__ float g_wqkv[DM * 3 * DM];       // packed [e][3072]
__device__ float g_bqkv[3 * DM];

// ---------------- layernorm: one block per row -------------------------------
__global__ __launch_bounds__(256) void ln_kernel(const float* __restrict__ x,
                                                 const float* __restrict__ w,
                                                 const float* __restrict__ bb,
                                                 float* __restrict__ out)
{
    int row = blockIdx.x;
    int t = threadIdx.x;
    const float* xr = x + (size_t)row * DM;
    float4 xv = reinterpret_cast<const float4*>(xr)[t];
    float s  = xv.x + xv.y + xv.z + xv.w;
    float sq = xv.x*xv.x + xv.y*xv.y + xv.z*xv.z + xv.w*xv.w;
    #pragma unroll
    for (int off = 16; off > 0; off >>= 1) {
        s  += __shfl_xor_sync(0xffffffffu, s,  off);
        sq += __shfl_xor_sync(0xffffffffu, sq, off);
    }
    __shared__ float ss[8], sk[8];
    __shared__ float smean, sinv;
    if ((t & 31) == 0) { ss[t >> 5] = s; sk[t >> 5] = sq; }
    __syncthreads();
    if (t == 0) {
        float S = 0.f, Q = 0.f;
        #pragma unroll
        for (int i = 0; i < 8; i++) { S += ss[i]; Q += sk[i]; }
        float mean = S * (1.0f / DM);
        float var  = Q * (1.0f / DM) - mean * mean;
        smean = mean;
        sinv  = rsqrtf(var + 1e-5f);
    }
    __syncthreads();
    float mean = smean, inv = sinv;
    float4 wv = reinterpret_cast<const float4*>(w)[t];
    float4 bv = reinterpret_cast<const float4*>(bb)[t];
    float4 ov;
    ov.x = (xv.x - mean) * inv * wv.x + bv.x;
    ov.y = (xv.y - mean) * inv * wv.y + bv.y;
    ov.z = (xv.z - mean) * inv * wv.z + bv.z;
    ov.w = (xv.w - mean) * inv * wv.w + bv.w;
    reinterpret_cast<float4*>(out + (size_t)row * DM)[t] = ov;
}

// ---------------- pack QKV weights into one [1024 x 3072] matrix -------------
__global__ void pack_qkv_kernel(const float* __restrict__ Wq, const float* __restrict__ Wk,
                                const float* __restrict__ Wv, const float* __restrict__ Bq,
                                const float* __restrict__ Bk, const float* __restrict__ Bv)
{
    int idx = blockIdx.x * 256 + threadIdx.x;
    if (idx < DM * 3 * DM) {
        int e   = idx / (3 * DM);
        int cc  = idx % (3 * DM);
        int sel = cc / DM;
        int col = cc % DM;
        const float* W = (sel == 0) ? Wq : (sel == 1) ? Wk : Wv;
        g_wqkv[idx] = W[(size_t)(col >> 6) * DM * DH + (size_t)e * DH + (col & 63)];
    }
    if (idx < 3 * DM) {
        int sel = idx / DM, col = idx % DM;
        const float* Bp = (sel == 0) ? Bq : (sel == 1) ? Bk : Bv;
        g_bqkv[idx] = Bp[col];
    }
}

// ---------------- TF32 tensor-core GEMM 128x128x16 ---------------------------
// C[M,N] = A[M,K]*B[K,N] row-major. 8 warps (4m x 2n), warp tile 32x64.
// mma.m16n8k8.tf32, fp32 accumulate. Smem strides ≡ 8 (mod 32): the fragment
// gather pattern (bank = 8*tig + group) is conflict-free.
// mode 0: +bias   mode 1: +bias, exact GELU   mode 2: +bias, +add (residual)
#define BM 128
#define BN 128
#define BK 16
#define ASTR (BM + 8)
#define BSTR (BN + 8)

__device__ __forceinline__ unsigned f2tf(float v) {
    unsigned r;
    asm("cvt.rna.tf32.f32 %0, %1;" : "=r"(r) : "f"(v));
    return r;
}

__device__ __forceinline__ void mma_tf32(float* c, const unsigned* a, const unsigned* b) {
    asm volatile(
        "mma.sync.aligned.m16n8k8.row.col.f32.tf32.tf32.f32 "
        "{%0,%1,%2,%3}, {%4,%5,%6,%7}, {%8,%9}, {%0,%1,%2,%3};"
        : "+f"(c[0]), "+f"(c[1]), "+f"(c[2]), "+f"(c[3])
        : "r"(a[0]), "r"(a[1]), "r"(a[2]), "r"(a[3]), "r"(b[0]), "r"(b[1]));
}

__global__ __launch_bounds__(256) void tgemm_kernel(
    const float* __restrict__ A, const float* __restrict__ Bm,
    float* __restrict__ C, int M, int N, int K,
    const float* __restrict__ bias, const float* __restrict__ add, int mode)
{
    __shared__ unsigned As[BK * ASTR];
    __shared__ unsigned Bs[BK * BSTR];
    int t    = threadIdx.x;
    int lane = t & 31, wid = t >> 5;
    int wm   = (wid >> 1) * 32;           // warp m offset: 0,32,64,96
    int wn   = (wid & 1) * 64;            // warp n offset: 0,64
    int g    = lane >> 2, tig = lane & 3; // group row / thread-in-group
    int m0   = blockIdx.y * BM, n0 = blockIdx.x * BN;

    float acc[2][8][4];
    #pragma unroll
    for (int i = 0; i < 2; i++)
        #pragma unroll
        for (int j = 0; j < 8; j++)
            #pragma unroll
            for (int q = 0; q < 4; q++) acc[i][j][q] = 0.f;

    // gmem tile load: 2 float4 of A + 2 float4 of B per thread per chunk
    float4 pa[2], pb[2];
    int af_r[2], af_c[2], bf_r[2], bf_c[2];
    #pragma unroll
    for (int u = 0; u < 2; u++) {
        int f = t * 2 + u;
        af_r[u] = f >> 2;  af_c[u] = (f & 3) * 4;    // A tile: 128 rows x 4 float4
        bf_r[u] = f >> 5;  bf_c[u] = (f & 31) * 4;   // B tile: 16 rows x 32 float4
    }

    #pragma unroll 1
    for (int k0 = 0; k0 < K; k0 += BK) {
        // load this chunk (first iter) or use prefetched values pattern:
        #pragma unroll
        for (int u = 0; u < 2; u++) {
            pa[u] = *reinterpret_cast<const float4*>(A + (size_t)(m0 + af_r[u]) * K + k0 + af_c[u]);
            pb[u] = *reinterpret_cast<const float4*>(Bm + (size_t)(k0 + bf_r[u]) * N + n0 + bf_c[u]);
        }
        #pragma unroll
        for (int u = 0; u < 2; u++) {
            As[(af_c[u] + 0) * ASTR + af_r[u]] = f2tf(pa[u].x);
            As[(af_c[u] + 1) * ASTR + af_r[u]] = f2tf(pa[u].y);
            As[(af_c[u] + 2) * ASTR + af_r[u]] = f2tf(pa[u].z);
            As[(af_c[u] + 3) * ASTR + af_r[u]] = f2tf(pa[u].w);
            Bs[bf_r[u] * BSTR + bf_c[u] + 0] = f2tf(pb[u].x);
            Bs[bf_r[u] * BSTR + bf_c[u] + 1] = f2tf(pb[u].y);
            Bs[bf_r[u] * BSTR + bf_c[u] + 2] = f2tf(pb[u].z);
            Bs[bf_r[u] * BSTR + bf_c[u] + 3] = f2tf(pb[u].w);
        }
        __syncthreads();

        #pragma unroll
        for (int kk = 0; kk < BK; kk += 8) {
            unsigned a[2][4], b[8][2];
            #pragma unroll
            for (int i = 0; i < 2; i++) {
                int mr = wm + i * 16;
                a[i][0] = As[(kk + tig) * ASTR + mr + g];
                a[i][1] = As[(kk + tig) * ASTR + mr + g + 8];
                a[i][2] = As[(kk + tig + 4) * ASTR + mr + g];
                a[i][3] = As[(kk + tig + 4) * ASTR + mr + g + 8];
            }
            #pragma unroll
            for (int j = 0; j < 8; j++) {
                int nc = wn + j * 8 + g;
                b[j][0] = Bs[(kk + tig) * BSTR + nc];
                b[j][1] = Bs[(kk + tig + 4) * BSTR + nc];
            }
            #pragma unroll
            for (int i = 0; i < 2; i++)
                #pragma unroll
                for (int j = 0; j < 8; j++)
                    mma_tf32(acc[i][j], a[i], b[j]);
        }
        __syncthreads();
    }

    // epilogue: c0/c1 at (row, col), (row, col+1); c2/c3 at row+8
    #pragma unroll
    for (int i = 0; i < 2; i++) {
        int r0 = m0 + wm + i * 16 + g;
        int r1 = r0 + 8;
        #pragma unroll
        for (int j = 0; j < 8; j++) {
            int col = n0 + wn + j * 8 + 2 * tig;
            float b0 = bias[col], b1 = bias[col + 1];
            float v0 = acc[i][j][0] + b0, v1 = acc[i][j][1] + b1;
            float v2 = acc[i][j][2] + b0, v3 = acc[i][j][3] + b1;
            if (mode == 1) {
                v0 = 0.5f * v0 * (1.0f + erff(v0 * 0.70710678118654752f));
                v1 = 0.5f * v1 * (1.0f + erff(v1 * 0.70710678118654752f));
                v2 = 0.5f * v2 * (1.0f + erff(v2 * 0.70710678118654752f));
                v3 = 0.5f * v3 * (1.0f + erff(v3 * 0.70710678118654752f));
            } else if (mode == 2) {
                float2 a0 = *reinterpret_cast<const float2*>(add + (size_t)r0 * N + col);
                float2 a1 = *reinterpret_cast<const float2*>(add + (size_t)r1 * N + col);
                v0 += a0.x; v1 += a0.y; v2 += a1.x; v3 += a1.y;
            }
            *reinterpret_cast<float2*>(C + (size_t)r0 * N + col) = make_float2(v0, v1);
            *reinterpret_cast<float2*>(C + (size_t)r1 * N + col) = make_float2(v2, v3);
        }
    }
}

// ---------------- flash attention with EPS mask (full softmax over all k) ----
#define QT 64
#define KT 32
#define DHP (DH + 4)
#define KTP (KT + 4)

__global__ __launch_bounds__(256) void flash_kernel(const float* __restrict__ qkv,
                                                    float* __restrict__ ctx)
{
    __shared__ float Qs[QT][DHP];
    __shared__ float Ks[KT][DHP];
    __shared__ float Vs[KT][DHP];
    __shared__ float Ps[QT][KTP];

    int t  = threadIdx.x;
    int tx = t & 15, ty = t >> 4;
    int qt = blockIdx.x;
    int n  = blockIdx.y & (NH - 1);
    int b  = blockIdx.y >> 4;
    int q0 = qt * QT;
    const float* base = qkv + (size_t)b * SEQ * (3 * DM);

    for (int f = t; f < QT * 16; f += 256) {
        int r = f >> 4, c4 = f & 15;
        float4 v = *reinterpret_cast<const float4*>(base + (size_t)(q0 + r) * (3 * DM) + n * 64 + c4 * 4);
        v.x *= 0.125f; v.y *= 0.125f; v.z *= 0.125f; v.w *= 0.125f;
        *reinterpret_cast<float4*>(&Qs[r][c4 * 4]) = v;
    }

    float m[4], l[4], o[4][4];
    #pragma unroll
    for (int i = 0; i < 4; i++) {
        m[i] = -INFINITY; l[i] = 0.f;
        #pragma unroll
        for (int j = 0; j < 4; j++) o[i][j] = 0.f;
    }

    for (int k0 = 0; k0 < SEQ; k0 += KT) {   // EPS-mask quirk: ALL tiles contribute
        __syncthreads();
        for (int f = t; f < KT * 16; f += 256) {
            int r = f >> 4, c4 = f & 15;
            const float* g = base + (size_t)(k0 + r) * (3 * DM) + DM + n * 64 + c4 * 4;
            *reinterpret_cast<float4*>(&Ks[r][c4 * 4]) = *reinterpret_cast<const float4*>(g);
            *reinterpret_cast<float4*>(&Vs[r][c4 * 4]) = *reinterpret_cast<const float4*>(g + DM);
        }
        __syncthreads();

        float acc[4][2];
        #pragma unroll
        for (int i = 0; i < 4; i++) { acc[i][0] = 0.f; acc[i][1] = 0.f; }
        #pragma unroll
        for (int kk = 0; kk < DH; kk++) {
            float kv0 = Ks[tx][kk];
            float kv1 = Ks[tx + 16][kk];
            #pragma unroll
            for (int i = 0; i < 4; i++) {
                float qv = Qs[ty * 4 + i][kk];
                acc[i][0] += qv * kv0;
                acc[i][1] += qv * kv1;
            }
        }

        #pragma unroll
        for (int i = 0; i < 4; i++) {
            int qg = q0 + ty * 4 + i;
            float s0 = (qg < k0 + tx)      ? 1e-10f : acc[i][0];
            float s1 = (qg < k0 + tx + 16) ? 1e-10f : acc[i][1];
            float mt = fmaxf(s0, s1);
            #pragma unroll
            for (int msk = 1; msk < 16; msk <<= 1)
                mt = fmaxf(mt, __shfl_xor_sync(0xffffffffu, mt, msk));
            float mn = fmaxf(m[i], mt);
            float p0 = __expf(s0 - mn);
            float p1 = __expf(s1 - mn);
            float lt = p0 + p1;
            #pragma unroll
            for (int msk = 1; msk < 16; msk <<= 1)
                lt += __shfl_xor_sync(0xffffffffu, lt, msk);
            float corr = __expf(m[i] - mn);
            l[i] = l[i] * corr + lt;
            #pragma unroll
            for (int j = 0; j < 4; j++) o[i][j] *= corr;
            m[i] = mn;
            Ps[ty * 4 + i][tx]      = p0;
            Ps[ty * 4 + i][tx + 16] = p1;
        }
        __syncthreads();

        #pragma unroll
        for (int k = 0; k < KT; k++) {
            float p[4], vv[4];
            #pragma unroll
            for (int i = 0; i < 4; i++) p[i] = Ps[ty * 4 + i][k];
            #pragma unroll
            for (int j = 0; j < 4; j++) vv[j] = Vs[k][tx + 16 * j];
            #pragma unroll
            for (int i = 0; i < 4; i++)
                #pragma unroll
                for (int j = 0; j < 4; j++) o[i][j] += p[i] * vv[j];
        }
    }

    int brow = b * SEQ + q0;
    #pragma unroll
    for (int i = 0; i < 4; i++) {
        float invl = 1.0f / l[i];
        #pragma unroll
        for (int j = 0; j < 4; j++)
            ctx[(size_t)(brow + ty * 4 + i) * DM + n * 64 + tx + 16 * j] = o[i][j] * invl;
    }
}

// ---------------- launch -----------------------------------------------------
extern "C" void kernel_launch(void* const* d_in, const int* in_sizes, int n_in,
                              void* d_out, int out_size)
{
    const float* residual   = (const float*)d_in[0];
    const float* W_key      = (const float*)d_in[1];
    const float* W_query    = (const float*)d_in[2];
    const float* W_values   = (const float*)d_in[3];
    const float* W_attn_out = (const float*)d_in[4];
    const float* B_key      = (const float*)d_in[5];
    const float* B_query    = (const float*)d_in[6];
    const float* B_values   = (const float*)d_in[7];
    const float* B_attn_out = (const float*)d_in[8];
    const float* ln1_w      = (const float*)d_in[9];
    const float* ln1_b      = (const float*)d_in[10];
    const float* ln2_w      = (const float*)d_in[11];
    const float* ln2_b      = (const float*)d_in[12];
    const float* W_mlp_in   = (const float*)d_in[13];
    const float* W_mlp_out  = (const float*)d_in[14];
    const float* B_mlp_in   = (const float*)d_in[15];
    const float* B_mlp_out  = (const float*)d_in[16];
    float* out = (float*)d_out;

    float *xln, *qkvp, *ctxp, *midp, *yp, *hp, *wqkvp, *bqkvp;
    cudaGetSymbolAddress((void**)&xln,   g_xln);
    cudaGetSymbolAddress((void**)&qkvp,  g_qkv);
    cudaGetSymbolAddress((void**)&ctxp,  g_ctx);
    cudaGetSymbolAddress((void**)&midp,  g_mid);
    cudaGetSymbolAddress((void**)&yp,    g_y);
    cudaGetSymbolAddress((void**)&hp,    g_h);
    cudaGetSymbolAddress((void**)&wqkvp, g_wqkv);
    cudaGetSymbolAddress((void**)&bqkvp, g_bqkv);

    // 1. LN1
    ln_kernel<<<MROWS, 256>>>(residual, ln1_w, ln1_b, xln);
    // 2. pack QKV weights/biases
    pack_qkv_kernel<<<(DM * 3 * DM + 255) / 256, 256>>>(W_query, W_key, W_values,
                                                        B_query, B_key, B_values);
    // 3. QKV projection: [4096,1024] x [1024,3072]  (tf32 tensor cores)
    tgemm_kernel<<<dim3(3 * DM / BN, MROWS / BM), 256>>>(
        xln, wqkvp, qkvp, MROWS, 3 * DM, DM, bqkvp, nullptr, 0);
    // 4. attention (EPS-masked full softmax)
    flash_kernel<<<dim3(SEQ / QT, BATCH * NH), 256>>>(qkvp, ctxp);
    // 5. attn out projection + residual -> mid
    tgemm_kernel<<<dim3(DM / BN, MROWS / BM), 256>>>(
        ctxp, W_attn_out, midp, MROWS, DM, DM, B_attn_out, residual, 2);
    // 6. LN2
    ln_kernel<<<MROWS, 256>>>(midp, ln2_w, ln2_b, yp);
    // 7. MLP in + exact GELU
    tgemm_kernel<<<dim3(DMLP / BN, MROWS / BM), 256>>>(
        yp, W_mlp_in, hp, MROWS, DMLP, DM, B_mlp_in, nullptr, 1);
    // 8. MLP out + residual -> output
    tgemm_kernel<<<dim3(DM / BN, MROWS / BM), 256>>>(
        hp, W_mlp_out, out, MROWS, DM, DMLP, B_mlp_out, midp, 2);
}

// round 7
// speedup vs baseline: 3.2576x; 2.8655x over previous
#include <cuda_runtime.h>
#include <math.h>
#include <stdint.h>

#define MROWS 4096   // B * S
#define DM    1024
#define DH    64
#define NH    16
#define DMLP  4096
#define SEQ   2048
#define BATCH 2

// ---------------- scratch (static device globals; no runtime alloc) ----------
__device__ float g_xln   [MROWS * DM];
__device__ float g_qkv   [MROWS * 3 * DM];   // [row][{Q,K,V} x (n*64+h)]
__device__ float g_ctx   [MROWS * DM];
__device__ float g_mid   [MROWS * DM];
__device__ float g_y     [MROWS * DM];
__device__ float g_h     [MROWS * DMLP];
__device__ float g_wqkv_t[3 * DM * DM];      // [N=3072][K=1024]
__device__ float g_watt_t[DM * DM];          // [N=1024][K=1024]
__device__ float g_wmin_t[DMLP * DM];        // [N=4096][K=1024]
__device__ float g_wmout_t[DM * DMLP];       // [N=1024][K=4096]
__device__ float g_bqkv  [3 * DM];

// ---------------- helpers ----------------------------------------------------
__device__ __forceinline__ uint32_t smem_u32(const void* p) {
    uint32_t a;
    asm("{ .reg .u64 t; cvta.to.shared.u64 t, %1; cvt.u32.u64 %0, t; }" : "=r"(a) : "l"(p));
    return a;
}
__device__ __forceinline__ float rna_tf32(float v) {
    unsigned r; asm("cvt.rna.tf32.f32 %0, %1;" : "=r"(r) : "f"(v));
    return __uint_as_float(r);
}
__device__ __forceinline__ void cp_async16(uint32_t s, const float* g) {
    asm volatile("cp.async.cg.shared.global [%0], [%1], 16;" :: "r"(s), "l"(g));
}
#define CP_COMMIT() asm volatile("cp.async.commit_group;")
#define CP_WAIT(n)  asm volatile("cp.async.wait_group %0;" :: "n"(n))

// m16n8k8 tf32 mma; fragment layout validated in Round 2:
// A: {(g,t),(g+8,t),(g,t+4),(g+8,t+4)}  B: {(t,n),(t+4,n)}  C: {(g,2t),(g,2t+1),(g+8,2t),(g+8,2t+1)}
__device__ __forceinline__ void mma8(float* c, const float* a, float b0, float b1) {
    asm volatile(
        "mma.sync.aligned.m16n8k8.row.col.f32.tf32.tf32.f32 "
        "{%0,%1,%2,%3}, {%4,%5,%6,%7}, {%8,%9}, {%0,%1,%2,%3};"
        : "+f"(c[0]), "+f"(c[1]), "+f"(c[2]), "+f"(c[3])
        : "r"(__float_as_uint(a[0])), "r"(__float_as_uint(a[1])),
          "r"(__float_as_uint(a[2])), "r"(__float_as_uint(a[3])),
          "r"(__float_as_uint(b0)),  "r"(__float_as_uint(b1)));
}

// ---------------- layernorm (tf32-rounded output) ----------------------------
__global__ __launch_bounds__(256) void ln_kernel(const float* __restrict__ x,
                                                 const float* __restrict__ w,
                                                 const float* __restrict__ bb,
                                                 float* __restrict__ out)
{
    int row = blockIdx.x;
    int t = threadIdx.x;
    const float* xr = x + (size_t)row * DM;
    float4 xv = reinterpret_cast<const float4*>(xr)[t];
    float s  = xv.x + xv.y + xv.z + xv.w;
    float sq = xv.x*xv.x + xv.y*xv.y + xv.z*xv.z + xv.w*xv.w;
    #pragma unroll
    for (int off = 16; off > 0; off >>= 1) {
        s  += __shfl_xor_sync(0xffffffffu, s,  off);
        sq += __shfl_xor_sync(0xffffffffu, sq, off);
    }
    __shared__ float ss[8], sk[8];
    __shared__ float smean, sinv;
    if ((t & 31) == 0) { ss[t >> 5] = s; sk[t >> 5] = sq; }
    __syncthreads();
    if (t == 0) {
        float S = 0.f, Q = 0.f;
        #pragma unroll
        for (int i = 0; i < 8; i++) { S += ss[i]; Q += sk[i]; }
        float mean = S * (1.0f / DM);
        float var  = Q * (1.0f / DM) - mean * mean;
        smean = mean;
        sinv  = rsqrtf(var + 1e-5f);
    }
    __syncthreads();
    float mean = smean, inv = sinv;
    float4 wv = reinterpret_cast<const float4*>(w)[t];
    float4 bv = reinterpret_cast<const float4*>(bb)[t];
    float4 ov;
    ov.x = rna_tf32((xv.x - mean) * inv * wv.x + bv.x);
    ov.y = rna_tf32((xv.y - mean) * inv * wv.y + bv.y);
    ov.z = rna_tf32((xv.z - mean) * inv * wv.z + bv.z);
    ov.w = rna_tf32((xv.w - mean) * inv * wv.w + bv.w);
    reinterpret_cast<float4*>(out + (size_t)row * DM)[t] = ov;
}

// ---------------- weight transposes (to [N][K], tf32-rounded) ----------------
__global__ void transpose_kernel(const float* __restrict__ in, float* __restrict__ out,
                                 int R, int C)
{
    __shared__ float tile[32][33];
    int r0 = blockIdx.y * 32, c0 = blockIdx.x * 32;
    int tx = threadIdx.x, ty = threadIdx.y;
    #pragma unroll
    for (int i = 0; i < 32; i += 8)
        tile[ty + i][tx] = in[(size_t)(r0 + ty + i) * C + c0 + tx];
    __syncthreads();
    #pragma unroll
    for (int i = 0; i < 32; i += 8)
        out[(size_t)(c0 + ty + i) * R + r0 + tx] = rna_tf32(tile[tx][ty + i]);
}

// QKV: g_wqkv_t[(sel*1024 + n*64 + h)][e] = W_sel[n][e][h]
__global__ void qkv_t_kernel(const float* __restrict__ Wq, const float* __restrict__ Wk,
                             const float* __restrict__ Wv)
{
    __shared__ float tile[32][33];
    int b   = blockIdx.z;
    int sel = b >> 4, n = b & 15;
    const float* W = (sel == 0) ? Wq : (sel == 1) ? Wk : Wv;
    const float* src = W + (size_t)n * DM * DH;       // [E=1024][H=64]
    int e0 = blockIdx.x * 32, h0 = blockIdx.y * 32;
    int tx = threadIdx.x, ty = threadIdx.y;
    #pragma unroll
    for (int i = 0; i < 32; i += 8)
        tile[ty + i][tx] = src[(size_t)(e0 + ty + i) * DH + h0 + tx];
    __syncthreads();
    #pragma unroll
    for (int i = 0; i < 32; i += 8)
        g_wqkv_t[(size_t)(sel * DM + n * 64 + h0 + ty + i) * DM + e0 + tx] =
            rna_tf32(tile[tx][ty + i]);
}

__global__ void bias_pack_kernel(const float* __restrict__ Bq, const float* __restrict__ Bk,
                                 const float* __restrict__ Bv)
{
    int idx = blockIdx.x * 256 + threadIdx.x;
    if (idx < 3 * DM) {
        int sel = idx / DM, col = idx % DM;
        const float* Bp = (sel == 0) ? Bq : (sel == 1) ? Bk : Bv;
        g_bqkv[idx] = Bp[col];
    }
}

// ---------------- pipelined tf32 mma GEMM ------------------------------------
// C[M,N] = A[M,K] * Bt[N,K]^T. Block 128x128, 8 warps (4m x 2n), warp 32x64.
// BK=16, 3-stage cp.async pipeline. Inputs pre-rounded to tf32 by producers.
// mode 0: +bias,round  1: +bias,GELU,round  2: +bias,+add
#define GSTR 20
#define GSTG 5120   // floats per stage (2 * 128*20)

__global__ __launch_bounds__(256) void mgemm(
    const float* __restrict__ A, const float* __restrict__ Bt,
    float* __restrict__ C, int M, int N, int K,
    const float* __restrict__ bias, const float* __restrict__ add, int mode)
{
    extern __shared__ float dsm[];
    uint32_t sb = smem_u32(dsm);
    int t    = threadIdx.x;
    int lane = t & 31, wid = t >> 5;
    int g    = lane >> 2, tig = lane & 3;
    int wm   = (wid >> 1) * 32;
    int wn   = (wid & 1) * 64;
    int m0   = blockIdx.y * 128, n0 = blockIdx.x * 128;
    int NC   = K >> 4;

    float acc[2][8][4];
    #pragma unroll
    for (int i = 0; i < 2; i++)
        #pragma unroll
        for (int j = 0; j < 8; j++)
            #pragma unroll
            for (int q = 0; q < 4; q++) acc[i][j][q] = 0.f;

    // per-thread cp.async slots: 4 x 16B per stage (A 512 + B 512 over 256 thr)
    uint32_t so[4];
    const float* gp[4];
    #pragma unroll
    for (int u = 0; u < 4; u++) {
        int idx = u * 256 + t;
        bool isB = idx >= 512;
        int v = isB ? idx - 512 : idx;
        int r = v >> 2, w = v & 3;
        so[u] = (uint32_t)(((isB ? 2560 : 0) + r * GSTR + w * 4) * 4);
        gp[u] = (isB ? Bt + (size_t)(n0 + r) * K : A + (size_t)(m0 + r) * K) + w * 4;
    }

    // prologue: stages 0,1
    #pragma unroll
    for (int c = 0; c < 2; c++) {
        uint32_t base = sb + c * GSTG * 4;
        #pragma unroll
        for (int u = 0; u < 4; u++) cp_async16(base + so[u], gp[u] + c * 16);
        CP_COMMIT();
    }

    for (int c = 0; c < NC; c++) {
        CP_WAIT(1);
        __syncthreads();
        const float* As = dsm + (c % 3) * GSTG;
        const float* Bs = As + 2560;
        #pragma unroll
        for (int kk = 0; kk < 16; kk += 8) {
            float a[2][4];
            #pragma unroll
            for (int i = 0; i < 2; i++) {
                int mr = wm + i * 16 + g;
                a[i][0] = As[mr * GSTR + kk + tig];
                a[i][1] = As[(mr + 8) * GSTR + kk + tig];
                a[i][2] = As[mr * GSTR + kk + tig + 4];
                a[i][3] = As[(mr + 8) * GSTR + kk + tig + 4];
            }
            #pragma unroll
            for (int j = 0; j < 8; j++) {
                int nr = wn + j * 8 + g;
                float b0 = Bs[nr * GSTR + kk + tig];
                float b1 = Bs[nr * GSTR + kk + tig + 4];
                #pragma unroll
                for (int i = 0; i < 2; i++) mma8(acc[i][j], a[i], b0, b1);
            }
        }
        __syncthreads();
        if (c + 2 < NC) {
            uint32_t base = sb + ((c + 2) % 3) * GSTG * 4;
            #pragma unroll
            for (int u = 0; u < 4; u++) cp_async16(base + so[u], gp[u] + (c + 2) * 16);
        }
        CP_COMMIT();
    }

    // epilogue (layout validated in Round 2)
    #pragma unroll
    for (int i = 0; i < 2; i++) {
        int r0 = m0 + wm + i * 16 + g;
        int r1 = r0 + 8;
        #pragma unroll
        for (int j = 0; j < 8; j++) {
            int col = n0 + wn + j * 8 + 2 * tig;
            float b0 = bias[col], b1 = bias[col + 1];
            float v0 = acc[i][j][0] + b0, v1 = acc[i][j][1] + b1;
            float v2 = acc[i][j][2] + b0, v3 = acc[i][j][3] + b1;
            if (mode == 0) {
                v0 = rna_tf32(v0); v1 = rna_tf32(v1);
                v2 = rna_tf32(v2); v3 = rna_tf32(v3);
            } else if (mode == 1) {
                v0 = rna_tf32(0.5f * v0 * (1.0f + erff(v0 * 0.70710678118654752f)));
                v1 = rna_tf32(0.5f * v1 * (1.0f + erff(v1 * 0.70710678118654752f)));
                v2 = rna_tf32(0.5f * v2 * (1.0f + erff(v2 * 0.70710678118654752f)));
                v3 = rna_tf32(0.5f * v3 * (1.0f + erff(v3 * 0.70710678118654752f)));
            } else {
                float2 a0 = *reinterpret_cast<const float2*>(add + (size_t)r0 * N + col);
                float2 a1 = *reinterpret_cast<const float2*>(add + (size_t)r1 * N + col);
                v0 += a0.x; v1 += a0.y; v2 += a1.x; v3 += a1.y;
            }
            *reinterpret_cast<float2*>(C + (size_t)r0 * N + col) = make_float2(v0, v1);
            *reinterpret_cast<float2*>(C + (size_t)r1 * N + col) = make_float2(v2, v3);
        }
    }
}

// ---------------- tensor-core flash attention (EPS mask, full softmax) -------
// QT=128 rows/block, KT=32, 8 warps each owning 16 q rows. Q frags preloaded
// to registers (scaled 1/8). K smem str 68, V str 72. Ps overlaid on Q smem
// (str 36). cp.async double-buffered K/V. FULL 64-wide rows (R5 bug fixed).
#define KQSTR 68
#define VSTR  72
#define PSTR  36
#define QPF   (128 * KQSTR)            // 8704 floats
#define KOFF(s) (QPF + (s) * (32 * KQSTR))
#define VOFF(s) (QPF + 2 * (32 * KQSTR) + (s) * (32 * VSTR))
#define FLASH_SMEM ((QPF + 2 * 32 * KQSTR + 2 * 32 * VSTR) * 4)   // 70656 B

__global__ __launch_bounds__(256) void flash_mma(const float* __restrict__ qkv,
                                                 float* __restrict__ ctx)
{
    extern __shared__ float dsm[];
    uint32_t sb = smem_u32(dsm);
    int t    = threadIdx.x;
    int lane = t & 31, wid = t >> 5;
    int g    = lane >> 2, tig = lane & 3;
    int n    = blockIdx.y & (NH - 1);
    int b    = blockIdx.y >> 4;
    int q0   = blockIdx.x * 128;
    const float* base = qkv + (size_t)b * SEQ * (3 * DM);

    // ---- prologue: Q tile (128 rows x 64 floats = 2048 x 16B chunks)
    #pragma unroll
    for (int u = 0; u < 8; u++) {
        int idx = u * 256 + t;
        int r = idx >> 4, w = idx & 15;
        cp_async16(sb + (uint32_t)((r * KQSTR + w * 4) * 4),
                   base + (size_t)(q0 + r) * (3 * DM) + n * 64 + w * 4);
    }
    CP_COMMIT();
    // KV stages 0,1: per stage 32 rows x 16 chunks; t<128 does K, t>=128 does V
    {
        int tt = t & 127;
        #pragma unroll
        for (int s = 0; s < 2; s++) {
            #pragma unroll
            for (int u = 0; u < 4; u++) {
                int idx = u * 128 + tt;
                int r = idx >> 4, w = idx & 15;
                const float* gsrc = base + (size_t)(s * 32 + r) * (3 * DM) + n * 64 + w * 4;
                if (t < 128)
                    cp_async16(sb + (uint32_t)((KOFF(s) + r * KQSTR + w * 4) * 4), gsrc + DM);
                else
                    cp_async16(sb + (uint32_t)((VOFF(s) + r * VSTR + w * 4) * 4), gsrc + 2 * DM);
            }
            CP_COMMIT();
        }
    }
    CP_WAIT(2);
    __syncthreads();

    // ---- preload Q fragments (x 1/sqrt(64)), then free Q region for Ps
    float qa[8][4];
    int qr = 16 * wid + g;
    #pragma unroll
    for (int ks = 0; ks < 8; ks++) {
        qa[ks][0] = dsm[qr * KQSTR + ks * 8 + tig] * 0.125f;
        qa[ks][1] = dsm[(qr + 8) * KQSTR + ks * 8 + tig] * 0.125f;
        qa[ks][2] = dsm[qr * KQSTR + ks * 8 + tig + 4] * 0.125f;
        qa[ks][3] = dsm[(qr + 8) * KQSTR + ks * 8 + tig + 4] * 0.125f;
    }
    float* Ps = dsm;   // overlay (first barrier below orders qa reads vs Ps writes)

    float o[8][4];
    #pragma unroll
    for (int j = 0; j < 8; j++)
        #pragma unroll
        for (int q = 0; q < 4; q++) o[j][q] = 0.f;
    float m0r = -INFINITY, m1r = -INFINITY, l0 = 0.f, l1 = 0.f;

    int qg0 = q0 + 16 * wid + g;
    int qg1 = qg0 + 8;

    for (int c = 0; c < SEQ / 32; c++) {     // EPS-mask quirk: ALL tiles
        CP_WAIT(1);
        __syncthreads();
        const float* Ks = dsm + KOFF(c & 1);
        const float* Vs = dsm + VOFF(c & 1);

        // S = Q K^T  (warp: 16 q rows x 32 k cols)
        float sc[4][4];
        #pragma unroll
        for (int j = 0; j < 4; j++)
            #pragma unroll
            for (int q = 0; q < 4; q++) sc[j][q] = 0.f;
        #pragma unroll
        for (int ks = 0; ks < 8; ks++) {
            #pragma unroll
            for (int j = 0; j < 4; j++) {
                int kr = j * 8 + g;
                float b0 = Ks[kr * KQSTR + ks * 8 + tig];
                float b1 = Ks[kr * KQSTR + ks * 8 + tig + 4];
                mma8(sc[j], qa[ks], b0, b1);
            }
        }

        // mask + online softmax (rows qg0, qg1)
        int k0 = c * 32;
        float mt0 = -INFINITY, mt1 = -INFINITY;
        #pragma unroll
        for (int j = 0; j < 4; j++) {
            int kc = k0 + j * 8 + 2 * tig;
            if (qg0 < kc)     sc[j][0] = 1e-10f;
            if (qg0 < kc + 1) sc[j][1] = 1e-10f;
            if (qg1 < kc)     sc[j][2] = 1e-10f;
            if (qg1 < kc + 1) sc[j][3] = 1e-10f;
            mt0 = fmaxf(mt0, fmaxf(sc[j][0], sc[j][1]));
            mt1 = fmaxf(mt1, fmaxf(sc[j][2], sc[j][3]));
        }
        #pragma unroll
        for (int msk = 1; msk < 4; msk <<= 1) {
            mt0 = fmaxf(mt0, __shfl_xor_sync(0xffffffffu, mt0, msk));
            mt1 = fmaxf(mt1, __shfl_xor_sync(0xffffffffu, mt1, msk));
        }
        float mn0 = fmaxf(m0r, mt0), mn1 = fmaxf(m1r, mt1);
        float lt0 = 0.f, lt1 = 0.f;
        #pragma unroll
        for (int j = 0; j < 4; j++) {
            sc[j][0] = __expf(sc[j][0] - mn0);
            sc[j][1] = __expf(sc[j][1] - mn0);
            sc[j][2] = __expf(sc[j][2] - mn1);
            sc[j][3] = __expf(sc[j][3] - mn1);
            lt0 += sc[j][0] + sc[j][1];
            lt1 += sc[j][2] + sc[j][3];
        }
        #pragma unroll
        for (int msk = 1; msk < 4; msk <<= 1) {
            lt0 += __shfl_xor_sync(0xffffffffu, lt0, msk);
            lt1 += __shfl_xor_sync(0xffffffffu, lt1, msk);
        }
        float c0 = __expf(m0r - mn0), c1 = __expf(m1r - mn1);
        l0 = l0 * c0 + lt0;  l1 = l1 * c1 + lt1;
        m0r = mn0;  m1r = mn1;
        #pragma unroll
        for (int j = 0; j < 8; j++) {
            o[j][0] *= c0; o[j][1] *= c0;
            o[j][2] *= c1; o[j][3] *= c1;
        }

        // P -> smem (tf32-rounded)
        #pragma unroll
        for (int j = 0; j < 4; j++) {
            *reinterpret_cast<float2*>(&Ps[qr * PSTR + j * 8 + 2 * tig]) =
                make_float2(rna_tf32(sc[j][0]), rna_tf32(sc[j][1]));
            *reinterpret_cast<float2*>(&Ps[(qr + 8) * PSTR + j * 8 + 2 * tig]) =
                make_float2(rna_tf32(sc[j][2]), rna_tf32(sc[j][3]));
        }
        __syncwarp();

        // O += P V
        #pragma unroll
        for (int ks = 0; ks < 4; ks++) {
            float pa[4];
            pa[0] = Ps[qr * PSTR + ks * 8 + tig];
            pa[1] = Ps[(qr + 8) * PSTR + ks * 8 + tig];
            pa[2] = Ps[qr * PSTR + ks * 8 + tig + 4];
            pa[3] = Ps[(qr + 8) * PSTR + ks * 8 + tig + 4];
            #pragma unroll
            for (int hj = 0; hj < 8; hj++) {
                float b0 = Vs[(ks * 8 + tig) * VSTR + hj * 8 + g];
                float b1 = Vs[(ks * 8 + tig + 4) * VSTR + hj * 8 + g];
                mma8(o[hj], pa, b0, b1);
            }
        }
        __syncthreads();

        // prefetch KV stage c+2 into buffer c&1 (full 64-wide rows)
        if (c + 2 < SEQ / 32) {
            int tt = t & 127;
            #pragma unroll
            for (int u = 0; u < 4; u++) {
                int idx = u * 128 + tt;
                int r = idx >> 4, w = idx & 15;
                const float* gsrc = base + (size_t)((c + 2) * 32 + r) * (3 * DM) + n * 64 + w * 4;
                if (t < 128)
                    cp_async16(sb + (uint32_t)((KOFF(c & 1) + r * KQSTR + w * 4) * 4), gsrc + DM);
                else
                    cp_async16(sb + (uint32_t)((VOFF(c & 1) + r * VSTR + w * 4) * 4), gsrc + 2 * DM);
            }
        }
        CP_COMMIT();
    }

    // ---- writeback (tf32-rounded: ctx feeds the next GEMM's A operand)
    float inv0 = 1.0f / l0, inv1 = 1.0f / l1;
    size_t r0 = (size_t)(b * SEQ + q0 + 16 * wid + g) * DM;
    size_t r1 = r0 + 8 * DM;
    #pragma unroll
    for (int hj = 0; hj < 8; hj++) {
        int col = n * 64 + hj * 8 + 2 * tig;
        *reinterpret_cast<float2*>(ctx + r0 + col) =
            make_float2(rna_tf32(o[hj][0] * inv0), rna_tf32(o[hj][1] * inv0));
        *reinterpret_cast<float2*>(ctx + r1 + col) =
            make_float2(rna_tf32(o[hj][2] * inv1), rna_tf32(o[hj][3] * inv1));
    }
}

// ---------------- launch -----------------------------------------------------
extern "C" void kernel_launch(void* const* d_in, const int* in_sizes, int n_in,
                              void* d_out, int out_size)
{
    const float* residual   = (const float*)d_in[0];
    const float* W_key      = (const float*)d_in[1];
    const float* W_query    = (const float*)d_in[2];
    const float* W_values   = (const float*)d_in[3];
    const float* W_attn_out = (const float*)d_in[4];
    const float* B_key      = (const float*)d_in[5];
    const float* B_query    = (const float*)d_in[6];
    const float* B_values   = (const float*)d_in[7];
    const float* B_attn_out = (const float*)d_in[8];
    const float* ln1_w      = (const float*)d_in[9];
    const float* ln1_b      = (const float*)d_in[10];
    const float* ln2_w      = (const float*)d_in[11];
    const float* ln2_b      = (const float*)d_in[12];
    const float* W_mlp_in   = (const float*)d_in[13];
    const float* W_mlp_out  = (const float*)d_in[14];
    const float* B_mlp_in   = (const float*)d_in[15];
    const float* B_mlp_out  = (const float*)d_in[16];
    float* out = (float*)d_out;

    float *xln, *qkvp, *ctxp, *midp, *yp, *hp, *wqkvt, *watt, *wmin, *wmout, *bqkvp;
    cudaGetSymbolAddress((void**)&xln,   g_xln);
    cudaGetSymbolAddress((void**)&qkvp,  g_qkv);
    cudaGetSymbolAddress((void**)&ctxp,  g_ctx);
    cudaGetSymbolAddress((void**)&midp,  g_mid);
    cudaGetSymbolAddress((void**)&yp,    g_y);
    cudaGetSymbolAddress((void**)&hp,    g_h);
    cudaGetSymbolAddress((void**)&wqkvt, g_wqkv_t);
    cudaGetSymbolAddress((void**)&watt,  g_watt_t);
    cudaGetSymbolAddress((void**)&wmin,  g_wmin_t);
    cudaGetSymbolAddress((void**)&wmout, g_wmout_t);
    cudaGetSymbolAddress((void**)&bqkvp, g_bqkv);

    const int GS = 3 * GSTG * 4;   // 61440 B
    cudaFuncSetAttribute(mgemm,     cudaFuncAttributeMaxDynamicSharedMemorySize, GS);
    cudaFuncSetAttribute(flash_mma, cudaFuncAttributeMaxDynamicSharedMemorySize, FLASH_SMEM);

    dim3 t32x8(32, 8);

    // weight prep (deterministic every call)
    qkv_t_kernel<<<dim3(DM / 32, DH / 32, 48), t32x8>>>(W_query, W_key, W_values);
    bias_pack_kernel<<<12, 256>>>(B_query, B_key, B_values);
    transpose_kernel<<<dim3(DM / 32, DM / 32),  t32x8>>>(W_attn_out, watt, DM, DM);
    transpose_kernel<<<dim3(DMLP / 32, DM / 32), t32x8>>>(W_mlp_in,  wmin, DM, DMLP);
    transpose_kernel<<<dim3(DM / 32, DMLP / 32), t32x8>>>(W_mlp_out, wmout, DMLP, DM);

    // 1. LN1
    ln_kernel<<<MROWS, 256>>>(residual, ln1_w, ln1_b, xln);
    // 2. QKV projection [4096,1024]x[1024,3072]
    mgemm<<<dim3(3 * DM / 128, MROWS / 128), 256, GS>>>(
        xln, wqkvt, qkvp, MROWS, 3 * DM, DM, bqkvp, nullptr, 0);
    // 3. attention (EPS-masked full softmax, tensor cores)
    flash_mma<<<dim3(SEQ / 128, BATCH * NH), 256, FLASH_SMEM>>>(qkvp, ctxp);
    // 4. attn out projection + residual -> mid
    mgemm<<<dim3(DM / 128, MROWS / 128), 256, GS>>>(
        ctxp, watt, midp, MROWS, DM, DM, B_attn_out, residual, 2);
    // 5. LN2
    ln_kernel<<<MROWS, 256>>>(midp, ln2_w, ln2_b, yp);
    // 6. MLP in + exact GELU
    mgemm<<<dim3(DMLP / 128, MROWS / 128), 256, GS>>>(
        yp, wmin, hp, MROWS, DMLP, DM, B_mlp_in, nullptr, 1);
    // 7. MLP out + residual -> output
    mgemm<<<dim3(DM / 128, MROWS / 128), 256, GS>>>(
        hp, wmout, out, MROWS, DM, DMLP, B_mlp_out, midp, 2);
}

// round 8
// speedup vs baseline: 5.7956x; 1.7791x over previous
#include <cuda_runtime.h>
#include <cuda_fp16.h>
#include <math.h>
#include <stdint.h>

#define MROWS 4096   // B * S
#define DM    1024
#define DH    64
#define NH    16
#define DMLP  4096
#define SEQ   2048
#define BATCH 2

// ---------------- scratch (static device globals; no runtime alloc) ----------
__device__ __half g_xln   [MROWS * DM];
__device__ __half g_qkv   [MROWS * 3 * DM];   // [row][{Q,K,V} x (n*64+h)]
__device__ __half g_ctx   [MROWS * DM];
__device__ float  g_mid   [MROWS * DM];       // fp32: residual carrier
__device__ __half g_y     [MROWS * DM];
__device__ __half g_h     [MROWS * DMLP];
__device__ __half g_wqkv_t[3 * DM * DM];      // [N=3072][K=1024]
__device__ __half g_watt_t[DM * DM];          // [N=1024][K=1024]
__device__ __half g_wmin_t[DMLP * DM];        // [N=4096][K=1024]
__device__ __half g_wmout_t[DM * DMLP];       // [N=1024][K=4096]
__device__ float  g_bqkv  [3 * DM];

// ---------------- helpers ----------------------------------------------------
__device__ __forceinline__ uint32_t smem_u32(const void* p) {
    uint32_t a;
    asm("{ .reg .u64 t; cvta.to.shared.u64 t, %1; cvt.u32.u64 %0, t; }" : "=r"(a) : "l"(p));
    return a;
}
__device__ __forceinline__ void cp_async16(uint32_t s, const void* g) {
    asm volatile("cp.async.cg.shared.global [%0], [%1], 16;" :: "r"(s), "l"(g));
}
#define CP_COMMIT() asm volatile("cp.async.commit_group;")
#define CP_WAIT(n)  asm volatile("cp.async.wait_group %0;" :: "n"(n))

// mma.m16n8k16 f16 -> f32. Frag layout (PTX):
// A: a0=(g,2tig..+1) a1=(g+8,same) a2=(g,2tig+8..+9) a3=(g+8,k+8)
// B: b0=(k=2tig..+1, n=g) b1=(k+8, n=g)   C: c0/c1=(g,2tig/2tig+1) c2/c3=(g+8,..)
__device__ __forceinline__ void mma16816(float* c, const uint32_t* a,
                                         uint32_t b0, uint32_t b1) {
    asm volatile(
        "mma.sync.aligned.m16n8k16.row.col.f32.f16.f16.f32 "
        "{%0,%1,%2,%3}, {%4,%5,%6,%7}, {%8,%9}, {%0,%1,%2,%3};"
        : "+f"(c[0]), "+f"(c[1]), "+f"(c[2]), "+f"(c[3])
        : "r"(a[0]), "r"(a[1]), "r"(a[2]), "r"(a[3]), "r"(b0), "r"(b1));
}

// ---------------- layernorm: fp32 in -> half out ------------------------------
__global__ __launch_bounds__(256) void ln_kernel(const float* __restrict__ x,
                                                 const float* __restrict__ w,
                                                 const float* __restrict__ bb,
                                                 __half* __restrict__ out)
{
    int row = blockIdx.x;
    int t = threadIdx.x;
    const float* xr = x + (size_t)row * DM;
    float4 xv = reinterpret_cast<const float4*>(xr)[t];
    float s  = xv.x + xv.y + xv.z + xv.w;
    float sq = xv.x*xv.x + xv.y*xv.y + xv.z*xv.z + xv.w*xv.w;
    #pragma unroll
    for (int off = 16; off > 0; off >>= 1) {
        s  += __shfl_xor_sync(0xffffffffu, s,  off);
        sq += __shfl_xor_sync(0xffffffffu, sq, off);
    }
    __shared__ float ss[8], sk[8];
    __shared__ float smean, sinv;
    if ((t & 31) == 0) { ss[t >> 5] = s; sk[t >> 5] = sq; }
    __syncthreads();
    if (t == 0) {
        float S = 0.f, Q = 0.f;
        #pragma unroll
        for (int i = 0; i < 8; i++) { S += ss[i]; Q += sk[i]; }
        float mean = S * (1.0f / DM);
        float var  = Q * (1.0f / DM) - mean * mean;
        smean = mean;
        sinv  = rsqrtf(var + 1e-5f);
    }
    __syncthreads();
    float mean = smean, inv = sinv;
    float4 wv = reinterpret_cast<const float4*>(w)[t];
    float4 bv = reinterpret_cast<const float4*>(bb)[t];
    __half2* o2 = reinterpret_cast<__half2*>(out + (size_t)row * DM);
    o2[2 * t]     = __floats2half2_rn((xv.x - mean) * inv * wv.x + bv.x,
                                      (xv.y - mean) * inv * wv.y + bv.y);
    o2[2 * t + 1] = __floats2half2_rn((xv.z - mean) * inv * wv.z + bv.z,
                                      (xv.w - mean) * inv * wv.w + bv.w);
}

// ---------------- weight transposes (to [N][K], half) -------------------------
__global__ void transpose_kernel(const float* __restrict__ in, __half* __restrict__ out,
                                 int R, int C)
{
    __shared__ float tile[32][33];
    int r0 = blockIdx.y * 32, c0 = blockIdx.x * 32;
    int tx = threadIdx.x, ty = threadIdx.y;
    #pragma unroll
    for (int i = 0; i < 32; i += 8)
        tile[ty + i][tx] = in[(size_t)(r0 + ty + i) * C + c0 + tx];
    __syncthreads();
    #pragma unroll
    for (int i = 0; i < 32; i += 8)
        out[(size_t)(c0 + ty + i) * R + r0 + tx] = __float2half_rn(tile[tx][ty + i]);
}

// QKV: g_wqkv_t[(sel*1024 + n*64 + h)][e] = W_sel[n][e][h]; query scaled by 1/8
__global__ void qkv_t_kernel(const float* __restrict__ Wq, const float* __restrict__ Wk,
                             const float* __restrict__ Wv)
{
    __shared__ float tile[32][33];
    int b   = blockIdx.z;
    int sel = b >> 4, n = b & 15;
    const float* W = (sel == 0) ? Wq : (sel == 1) ? Wk : Wv;
    float scale = (sel == 0) ? 0.125f : 1.0f;
    const float* src = W + (size_t)n * DM * DH;       // [E=1024][H=64]
    int e0 = blockIdx.x * 32, h0 = blockIdx.y * 32;
    int tx = threadIdx.x, ty = threadIdx.y;
    #pragma unroll
    for (int i = 0; i < 32; i += 8)
        tile[ty + i][tx] = src[(size_t)(e0 + ty + i) * DH + h0 + tx];
    __syncthreads();
    #pragma unroll
    for (int i = 0; i < 32; i += 8)
        g_wqkv_t[(size_t)(sel * DM + n * 64 + h0 + ty + i) * DM + e0 + tx] =
            __float2half_rn(tile[tx][ty + i] * scale);
}

__global__ void bias_pack_kernel(const float* __restrict__ Bq, const float* __restrict__ Bk,
                                 const float* __restrict__ Bv)
{
    int idx = blockIdx.x * 256 + threadIdx.x;
    if (idx < 3 * DM) {
        int sel = idx / DM, col = idx % DM;
        const float* Bp = (sel == 0) ? Bq : (sel == 1) ? Bk : Bv;
        g_bqkv[idx] = Bp[col] * (sel == 0 ? 0.125f : 1.0f);
    }
}

// ---------------- pipelined fp16 mma GEMM --------------------------------------
// C[M,N] = A[M,K] * Bt[N,K]^T, A/Bt half. Block 128x128, 8 warps (4m x 2n),
// warp 32x64. BK=32 per stage, 3-stage cp.async. Row stride 40 halves (20 u32):
// frag gathers hit banks 20g+tig -> conflict-free.
// mode 0: +bias -> half   1: +bias,GELU -> half   2: +bias,+add(f32) -> f32
#define GSTGB 20480   // bytes per stage: (128+128) rows * 40 halves * 2

__global__ __launch_bounds__(256) void mgemm(
    const __half* __restrict__ A, const __half* __restrict__ Bt,
    void* __restrict__ Cv, int M, int N, int K,
    const float* __restrict__ bias, const float* __restrict__ add, int mode)
{
    extern __shared__ __align__(16) unsigned char smb[];
    uint32_t sb = smem_u32(smb);
    int t    = threadIdx.x;
    int lane = t & 31, wid = t >> 5;
    int g    = lane >> 2, tig = lane & 3;
    int wm   = (wid >> 1) * 32;
    int wn   = (wid & 1) * 64;
    int m0   = blockIdx.y * 128, n0 = blockIdx.x * 128;
    int NC   = K >> 5;

    float acc[2][8][4];
    #pragma unroll
    for (int i = 0; i < 2; i++)
        #pragma unroll
        for (int j = 0; j < 8; j++)
            #pragma unroll
            for (int q = 0; q < 4; q++) acc[i][j][q] = 0.f;

    // cp.async slots: 4 x 16B (8 halves) per thread per stage
    uint32_t so[4];
    const __half* gp[4];
    #pragma unroll
    for (int u = 0; u < 4; u++) {
        int idx = u * 256 + t;
        bool isB = idx >= 512;
        int v = idx & 511;
        int r = v >> 2, w = v & 3;            // 4 chunks x 8 halves = 32-k row
        so[u] = (uint32_t)(((isB ? 5120 : 0) + r * 40 + w * 8) * 2);
        gp[u] = (isB ? Bt + (size_t)(n0 + r) * K : A + (size_t)(m0 + r) * K) + w * 8;
    }

    #pragma unroll
    for (int c = 0; c < 2; c++) {
        uint32_t base = sb + c * GSTGB;
        #pragma unroll
        for (int u = 0; u < 4; u++) cp_async16(base + so[u], gp[u] + c * 32);
        CP_COMMIT();
    }

    for (int c = 0; c < NC; c++) {
        CP_WAIT(1);
        __syncthreads();
        const uint32_t* As2 = reinterpret_cast<const uint32_t*>(smb + (c % 3) * GSTGB);
        const uint32_t* Bs2 = As2 + 2560;
        #pragma unroll
        for (int ko = 0; ko < 16; ko += 8) {   // two k16 steps per 32-k chunk
            uint32_t a[2][4];
            #pragma unroll
            for (int i = 0; i < 2; i++) {
                int mr = wm + i * 16 + g;
                a[i][0] = As2[mr * 20 + ko + tig];
                a[i][1] = As2[(mr + 8) * 20 + ko + tig];
                a[i][2] = As2[mr * 20 + ko + tig + 4];
                a[i][3] = As2[(mr + 8) * 20 + ko + tig + 4];
            }
            #pragma unroll
            for (int j = 0; j < 8; j++) {
                int nr = wn + j * 8 + g;
                uint32_t b0 = Bs2[nr * 20 + ko + tig];
                uint32_t b1 = Bs2[nr * 20 + ko + tig + 4];
                #pragma unroll
                for (int i = 0; i < 2; i++) mma16816(acc[i][j], a[i], b0, b1);
            }
        }
        __syncthreads();
        if (c + 2 < NC) {
            uint32_t base = sb + ((c + 2) % 3) * GSTGB;
            #pragma unroll
            for (int u = 0; u < 4; u++) cp_async16(base + so[u], gp[u] + (c + 2) * 32);
        }
        CP_COMMIT();
    }

    // epilogue
    #pragma unroll
    for (int i = 0; i < 2; i++) {
        int r0 = m0 + wm + i * 16 + g;
        int r1 = r0 + 8;
        #pragma unroll
        for (int j = 0; j < 8; j++) {
            int col = n0 + wn + j * 8 + 2 * tig;
            float b0 = bias[col], b1 = bias[col + 1];
            float v0 = acc[i][j][0] + b0, v1 = acc[i][j][1] + b1;
            float v2 = acc[i][j][2] + b0, v3 = acc[i][j][3] + b1;
            if (mode == 1) {
                v0 = 0.5f * v0 * (1.0f + erff(v0 * 0.70710678118654752f));
                v1 = 0.5f * v1 * (1.0f + erff(v1 * 0.70710678118654752f));
                v2 = 0.5f * v2 * (1.0f + erff(v2 * 0.70710678118654752f));
                v3 = 0.5f * v3 * (1.0f + erff(v3 * 0.70710678118654752f));
            }
            if (mode == 2) {
                float* C = (float*)Cv;
                float2 a0 = *reinterpret_cast<const float2*>(add + (size_t)r0 * N + col);
                float2 a1 = *reinterpret_cast<const float2*>(add + (size_t)r1 * N + col);
                *reinterpret_cast<float2*>(C + (size_t)r0 * N + col) = make_float2(v0 + a0.x, v1 + a0.y);
                *reinterpret_cast<float2*>(C + (size_t)r1 * N + col) = make_float2(v2 + a1.x, v3 + a1.y);
            } else {
                __half* C = (__half*)Cv;
                *reinterpret_cast<__half2*>(C + (size_t)r0 * N + col) = __floats2half2_rn(v0, v1);
                *reinterpret_cast<__half2*>(C + (size_t)r1 * N + col) = __floats2half2_rn(v2, v3);
            }
        }
    }
}

// ---------------- fp16 tensor-core flash attention (EPS mask, full softmax) ---
// QT=128, KT=32, 8 warps x 16 q rows. Q pre-scaled by 1/8 at projection.
// Q/K stride 72 halves (36 u32: banks 4g+tig). V stride 72, read via
// ldmatrix.x4.trans. P overlay on Q region, stride 40 halves.
#define QSTRH 72
#define KVSTRH 72
#define PSTRU 20
#define KOFFH(s) (9216 + (s) * 2304)
#define VOFFH(s) (13824 + (s) * 2304)
#define FLASH_SMEM 36864

__global__ __launch_bounds__(256) void flash_mma(const __half* __restrict__ qkv,
                                                 __half* __restrict__ ctx)
{
    extern __shared__ __align__(16) unsigned char smb[];
    __half* sh = reinterpret_cast<__half*>(smb);
    uint32_t sb = smem_u32(smb);
    int t    = threadIdx.x;
    int lane = t & 31, wid = t >> 5;
    int g    = lane >> 2, tig = lane & 3;
    int n    = blockIdx.y & (NH - 1);
    int b    = blockIdx.y >> 4;
    int q0   = blockIdx.x * 128;
    const __half* base = qkv + (size_t)b * SEQ * (3 * DM);

    // Q tile: 128 rows x 64 halves = 1024 chunks of 16B
    #pragma unroll
    for (int u = 0; u < 4; u++) {
        int idx = u * 256 + t;
        int r = idx >> 3, w = idx & 7;
        cp_async16(sb + (uint32_t)((r * QSTRH + w * 8) * 2),
                   base + (size_t)(q0 + r) * (3 * DM) + n * 64 + w * 8);
    }
    CP_COMMIT();
    // KV stages 0,1: 32 rows x 8 chunks each; t<128 K, t>=128 V
    {
        int tt = t & 127;
        #pragma unroll
        for (int s = 0; s < 2; s++) {
            #pragma unroll
            for (int u = 0; u < 2; u++) {
                int idx = u * 128 + tt;
                int r = idx >> 3, w = idx & 7;
                const __half* gsrc = base + (size_t)(s * 32 + r) * (3 * DM) + n * 64 + w * 8;
                if (t < 128)
                    cp_async16(sb + (uint32_t)((KOFFH(s) + r * KVSTRH + w * 8) * 2), gsrc + DM);
                else
                    cp_async16(sb + (uint32_t)((VOFFH(s) + r * KVSTRH + w * 8) * 2), gsrc + 2 * DM);
            }
            CP_COMMIT();
        }
    }
    CP_WAIT(2);
    __syncthreads();

    // preload Q fragments (already 1/8-scaled); then Q region becomes P
    const uint32_t* Qu = reinterpret_cast<const uint32_t*>(smb);
    uint32_t qa[4][4];
    int qr = 16 * wid + g;
    #pragma unroll
    for (int ks = 0; ks < 4; ks++) {
        qa[ks][0] = Qu[qr * 36 + ks * 8 + tig];
        qa[ks][1] = Qu[(qr + 8) * 36 + ks * 8 + tig];
        qa[ks][2] = Qu[qr * 36 + ks * 8 + tig + 4];
        qa[ks][3] = Qu[(qr + 8) * 36 + ks * 8 + tig + 4];
    }
    uint32_t* Pu = reinterpret_cast<uint32_t*>(smb);   // overlay

    float o[8][4];
    #pragma unroll
    for (int j = 0; j < 8; j++)
        #pragma unroll
        for (int q = 0; q < 4; q++) o[j][q] = 0.f;
    float m0r = -INFINITY, m1r = -INFINITY, l0 = 0.f, l1 = 0.f;

    int qg0 = q0 + 16 * wid + g;
    int qg1 = qg0 + 8;

    for (int c = 0; c < SEQ / 32; c++) {     // EPS-mask quirk: ALL tiles
        CP_WAIT(1);
        __syncthreads();
        const uint32_t* Ku = reinterpret_cast<const uint32_t*>(sh + KOFFH(c & 1));
        uint32_t vbase = sb + (uint32_t)(VOFFH(c & 1) * 2);

        // S = Q K^T : 16 mmas (4 n-groups x 4 k16 steps)
        float sc[4][4];
        #pragma unroll
        for (int j = 0; j < 4; j++)
            #pragma unroll
            for (int q = 0; q < 4; q++) sc[j][q] = 0.f;
        #pragma unroll
        for (int ks = 0; ks < 4; ks++)
            #pragma unroll
            for (int j = 0; j < 4; j++) {
                int kr = j * 8 + g;
                uint32_t b0 = Ku[kr * 36 + ks * 8 + tig];
                uint32_t b1 = Ku[kr * 36 + ks * 8 + tig + 4];
                mma16816(sc[j], qa[ks], b0, b1);
            }

        // mask + online softmax
        int k0 = c * 32;
        float mt0 = -INFINITY, mt1 = -INFINITY;
        #pragma unroll
        for (int j = 0; j < 4; j++) {
            int kc = k0 + j * 8 + 2 * tig;
            if (qg0 < kc)     sc[j][0] = 1e-10f;
            if (qg0 < kc + 1) sc[j][1] = 1e-10f;
            if (qg1 < kc)     sc[j][2] = 1e-10f;
            if (qg1 < kc + 1) sc[j][3] = 1e-10f;
            mt0 = fmaxf(mt0, fmaxf(sc[j][0], sc[j][1]));
            mt1 = fmaxf(mt1, fmaxf(sc[j][2], sc[j][3]));
        }
        #pragma unroll
        for (int msk = 1; msk < 4; msk <<= 1) {
            mt0 = fmaxf(mt0, __shfl_xor_sync(0xffffffffu, mt0, msk));
            mt1 = fmaxf(mt1, __shfl_xor_sync(0xffffffffu, mt1, msk));
        }
        float mn0 = fmaxf(m0r, mt0), mn1 = fmaxf(m1r, mt1);
        float lt0 = 0.f, lt1 = 0.f;
        #pragma unroll
        for (int j = 0; j < 4; j++) {
            sc[j][0] = __expf(sc[j][0] - mn0);
            sc[j][1] = __expf(sc[j][1] - mn0);
            sc[j][2] = __expf(sc[j][2] - mn1);
            sc[j][3] = __expf(sc[j][3] - mn1);
            lt0 += sc[j][0] + sc[j][1];
            lt1 += sc[j][2] + sc[j][3];
        }
        #pragma unroll
        for (int msk = 1; msk < 4; msk <<= 1) {
            lt0 += __shfl_xor_sync(0xffffffffu, lt0, msk);
            lt1 += __shfl_xor_sync(0xffffffffu, lt1, msk);
        }
        float c0 = __expf(m0r - mn0), c1 = __expf(m1r - mn1);
        l0 = l0 * c0 + lt0;  l1 = l1 * c1 + lt1;
        m0r = mn0;  m1r = mn1;
        #pragma unroll
        for (int j = 0; j < 8; j++) {
            o[j][0] *= c0; o[j][1] *= c0;
            o[j][2] *= c1; o[j][3] *= c1;
        }

        // P -> smem as half2 (C-frag pairs are contiguous)
        #pragma unroll
        for (int j = 0; j < 4; j++) {
            __half2 p01 = __floats2half2_rn(sc[j][0], sc[j][1]);
            __half2 p23 = __floats2half2_rn(sc[j][2], sc[j][3]);
            Pu[qr * PSTRU + j * 4 + tig]       = *reinterpret_cast<uint32_t*>(&p01);
            Pu[(qr + 8) * PSTRU + j * 4 + tig] = *reinterpret_cast<uint32_t*>(&p23);
        }
        __syncwarp();

        // O += P V : 16 mmas (2 k16 steps x 8 n-groups); V^T frags via ldmatrix.trans
        #pragma unroll
        for (int ks = 0; ks < 2; ks++) {
            uint32_t pa[4];
            pa[0] = Pu[qr * PSTRU + ks * 8 + tig];
            pa[1] = Pu[(qr + 8) * PSTRU + ks * 8 + tig];
            pa[2] = Pu[qr * PSTRU + ks * 8 + tig + 4];
            pa[3] = Pu[(qr + 8) * PSTRU + ks * 8 + tig + 4];
            #pragma unroll
            for (int cb = 0; cb < 4; cb++) {   // each call: 2 n-groups (16 cols)
                int tile = lane >> 3, lr = lane & 7;
                int row = ks * 16 + lr + (tile & 1) * 8;
                int col = cb * 16 + (tile >> 1) * 8;
                uint32_t addr = vbase + (uint32_t)((row * KVSTRH + col) * 2);
                uint32_t v0, v1, v2, v3;
                asm volatile(
                    "ldmatrix.sync.aligned.m8n8.x4.trans.shared.b16 {%0,%1,%2,%3}, [%4];"
                    : "=r"(v0), "=r"(v1), "=r"(v2), "=r"(v3) : "r"(addr));
                mma16816(o[cb * 2],     pa, v0, v1);
                mma16816(o[cb * 2 + 1], pa, v2, v3);
            }
        }
        __syncthreads();

        // prefetch KV stage c+2 into buffer c&1
        if (c + 2 < SEQ / 32) {
            int tt = t & 127;
            #pragma unroll
            for (int u = 0; u < 2; u++) {
                int idx = u * 128 + tt;
                int r = idx >> 3, w = idx & 7;
                const __half* gsrc = base + (size_t)((c + 2) * 32 + r) * (3 * DM) + n * 64 + w * 8;
                if (t < 128)
                    cp_async16(sb + (uint32_t)((KOFFH(c & 1) + r * KVSTRH + w * 8) * 2), gsrc + DM);
                else
                    cp_async16(sb + (uint32_t)((VOFFH(c & 1) + r * KVSTRH + w * 8) * 2), gsrc + 2 * DM);
            }
        }
        CP_COMMIT();
    }

    // writeback (half: feeds attn-out GEMM A operand)
    float inv0 = 1.0f / l0, inv1 = 1.0f / l1;
    size_t r0 = (size_t)(b * SEQ + q0 + 16 * wid + g) * DM;
    size_t r1 = r0 + 8 * DM;
    #pragma unroll
    for (int hj = 0; hj < 8; hj++) {
        int col = n * 64 + hj * 8 + 2 * tig;
        *reinterpret_cast<__half2*>(ctx + r0 + col) =
            __floats2half2_rn(o[hj][0] * inv0, o[hj][1] * inv0);
        *reinterpret_cast<__half2*>(ctx + r1 + col) =
            __floats2half2_rn(o[hj][2] * inv1, o[hj][3] * inv1);
    }
}

// ---------------- launch -----------------------------------------------------
extern "C" void kernel_launch(void* const* d_in, const int* in_sizes, int n_in,
                              void* d_out, int out_size)
{
    const float* residual   = (const float*)d_in[0];
    const float* W_key      = (const float*)d_in[1];
    const float* W_query    = (const float*)d_in[2];
    const float* W_values   = (const float*)d_in[3];
    const float* W_attn_out = (const float*)d_in[4];
    const float* B_key      = (const float*)d_in[5];
    const float* B_query    = (const float*)d_in[6];
    const float* B_values   = (const float*)d_in[7];
    const float* B_attn_out = (const float*)d_in[8];
    const float* ln1_w      = (const float*)d_in[9];
    const float* ln1_b      = (const float*)d_in[10];
    const float* ln2_w      = (const float*)d_in[11];
    const float* ln2_b      = (const float*)d_in[12];
    const float* W_mlp_in   = (const float*)d_in[13];
    const float* W_mlp_out  = (const float*)d_in[14];
    const float* B_mlp_in   = (const float*)d_in[15];
    const float* B_mlp_out  = (const float*)d_in[16];
    float* out = (float*)d_out;

    __half *xln, *qkvp, *ctxp, *yp, *hp, *wqkvt, *watt, *wmin, *wmout;
    float *midp, *bqkvp;
    cudaGetSymbolAddress((void**)&xln,   g_xln);
    cudaGetSymbolAddress((void**)&qkvp,  g_qkv);
    cudaGetSymbolAddress((void**)&ctxp,  g_ctx);
    cudaGetSymbolAddress((void**)&midp,  g_mid);
    cudaGetSymbolAddress((void**)&yp,    g_y);
    cudaGetSymbolAddress((void**)&hp,    g_h);
    cudaGetSymbolAddress((void**)&wqkvt, g_wqkv_t);
    cudaGetSymbolAddress((void**)&watt,  g_watt_t);
    cudaGetSymbolAddress((void**)&wmin,  g_wmin_t);
    cudaGetSymbolAddress((void**)&wmout, g_wmout_t);
    cudaGetSymbolAddress((void**)&bqkvp, g_bqkv);

    const int GS = 3 * GSTGB;   // 61440 B
    cudaFuncSetAttribute(mgemm,     cudaFuncAttributeMaxDynamicSharedMemorySize, GS);
    cudaFuncSetAttribute(flash_mma, cudaFuncAttributeMaxDynamicSharedMemorySize, FLASH_SMEM);

    dim3 t32x8(32, 8);

    // weight prep (deterministic every call)
    qkv_t_kernel<<<dim3(DM / 32, DH / 32, 48), t32x8>>>(W_query, W_key, W_values);
    bias_pack_kernel<<<12, 256>>>(B_query, B_key, B_values);
    transpose_kernel<<<dim3(DM / 32, DM / 32),  t32x8>>>(W_attn_out, watt, DM, DM);
    transpose_kernel<<<dim3(DMLP / 32, DM / 32), t32x8>>>(W_mlp_in,  wmin, DM, DMLP);
    transpose_kernel<<<dim3(DM / 32, DMLP / 32), t32x8>>>(W_mlp_out, wmout, DMLP, DM);

    // 1. LN1
    ln_kernel<<<MROWS, 256>>>(residual, ln1_w, ln1_b, xln);
    // 2. QKV projection [4096,1024]x[1024,3072]
    mgemm<<<dim3(3 * DM / 128, MROWS / 128), 256, GS>>>(
        xln, wqkvt, qkvp, MROWS, 3 * DM, DM, bqkvp, nullptr, 0);
    // 3. attention (EPS-masked full softmax, fp16 tensor cores)
    flash_mma<<<dim3(SEQ / 128, BATCH * NH), 256, FLASH_SMEM>>>(qkvp, ctxp);
    // 4. attn out projection + residual -> mid (fp32)
    mgemm<<<dim3(DM / 128, MROWS / 128), 256, GS>>>(
        ctxp, watt, midp, MROWS, DM, DM, B_attn_out, residual, 2);
    // 5. LN2
    ln_kernel<<<MROWS, 256>>>(midp, ln2_w, ln2_b, yp);
    // 6. MLP in + exact GELU
    mgemm<<<dim3(DMLP / 128, MROWS / 128), 256, GS>>>(
        yp, wmin, hp, MROWS, DMLP, DM, B_mlp_in, nullptr, 1);
    // 7. MLP out + residual -> output (fp32)
    mgemm<<<dim3(DM / 128, MROWS / 128), 256, GS>>>(
        hp, wmout, out, MROWS, DM, DMLP, B_mlp_out, midp, 2);
}

// round 9
// speedup vs baseline: 6.1795x; 1.0662x over previous
#include <cuda_runtime.h>
#include <cuda_fp16.h>
#include <math.h>
#include <stdint.h>

#define MROWS 4096   // B * S
#define DM    1024
#define DH    64
#define NH    16
#define DMLP  4096
#define SEQ   2048
#define BATCH 2

// ---------------- scratch (static device globals; no runtime alloc) ----------
__device__ __half g_xln   [MROWS * DM];
__device__ __half g_qkv   [MROWS * 3 * DM];   // [row][{Q,K,V} x (n*64+h)]
__device__ __half g_ctx   [MROWS * DM];
__device__ float  g_mid   [MROWS * DM];       // fp32: residual carrier
__device__ __half g_y     [MROWS * DM];
__device__ __half g_h     [MROWS * DMLP];
__device__ __half g_wqkv_t[3 * DM * DM];      // [N=3072][K=1024]
__device__ __half g_watt_t[DM * DM];          // [N=1024][K=1024]
__device__ __half g_wmin_t[DMLP * DM];        // [N=4096][K=1024]
__device__ __half g_wmout_t[DM * DMLP];       // [N=1024][K=4096]
__device__ float  g_bqkv  [3 * DM];

// ---------------- helpers ----------------------------------------------------
__device__ __forceinline__ uint32_t smem_u32(const void* p) {
    uint32_t a;
    asm("{ .reg .u64 t; cvta.to.shared.u64 t, %1; cvt.u32.u64 %0, t; }" : "=r"(a) : "l"(p));
    return a;
}
__device__ __forceinline__ void cp_async16(uint32_t s, const void* g) {
    asm volatile("cp.async.cg.shared.global [%0], [%1], 16;" :: "r"(s), "l"(g));
}
#define CP_COMMIT() asm volatile("cp.async.commit_group;")
#define CP_WAIT(n)  asm volatile("cp.async.wait_group %0;" :: "n"(n))

__device__ __forceinline__ void ldm_x4(uint32_t* r, uint32_t addr) {
    asm volatile("ldmatrix.sync.aligned.m8n8.x4.shared.b16 {%0,%1,%2,%3}, [%4];"
        : "=r"(r[0]), "=r"(r[1]), "=r"(r[2]), "=r"(r[3]) : "r"(addr));
}
__device__ __forceinline__ void ldm_x4_trans(uint32_t* r, uint32_t addr) {
    asm volatile("ldmatrix.sync.aligned.m8n8.x4.trans.shared.b16 {%0,%1,%2,%3}, [%4];"
        : "=r"(r[0]), "=r"(r[1]), "=r"(r[2]), "=r"(r[3]) : "r"(addr));
}

// mma.m16n8k16 f16 -> f32
__device__ __forceinline__ void mma16816(float* c, const uint32_t* a,
                                         uint32_t b0, uint32_t b1) {
    asm volatile(
        "mma.sync.aligned.m16n8k16.row.col.f32.f16.f16.f32 "
        "{%0,%1,%2,%3}, {%4,%5,%6,%7}, {%8,%9}, {%0,%1,%2,%3};"
        : "+f"(c[0]), "+f"(c[1]), "+f"(c[2]), "+f"(c[3])
        : "r"(a[0]), "r"(a[1]), "r"(a[2]), "r"(a[3]), "r"(b0), "r"(b1));
}

// ---------------- layernorm: fp32 in -> half out ------------------------------
__global__ __launch_bounds__(256) void ln_kernel(const float* __restrict__ x,
                                                 const float* __restrict__ w,
                                                 const float* __restrict__ bb,
                                                 __half* __restrict__ out)
{
    int row = blockIdx.x;
    int t = threadIdx.x;
    const float* xr = x + (size_t)row * DM;
    float4 xv = reinterpret_cast<const float4*>(xr)[t];
    float s  = xv.x + xv.y + xv.z + xv.w;
    float sq = xv.x*xv.x + xv.y*xv.y + xv.z*xv.z + xv.w*xv.w;
    #pragma unroll
    for (int off = 16; off > 0; off >>= 1) {
        s  += __shfl_xor_sync(0xffffffffu, s,  off);
        sq += __shfl_xor_sync(0xffffffffu, sq, off);
    }
    __shared__ float ss[8], sk[8];
    __shared__ float smean, sinv;
    if ((t & 31) == 0) { ss[t >> 5] = s; sk[t >> 5] = sq; }
    __syncthreads();
    if (t == 0) {
        float S = 0.f, Q = 0.f;
        #pragma unroll
        for (int i = 0; i < 8; i++) { S += ss[i]; Q += sk[i]; }
        float mean = S * (1.0f / DM);
        float var  = Q * (1.0f / DM) - mean * mean;
        smean = mean;
        sinv  = rsqrtf(var + 1e-5f);
    }
    __syncthreads();
    float mean = smean, inv = sinv;
    float4 wv = reinterpret_cast<const float4*>(w)[t];
    float4 bv = reinterpret_cast<const float4*>(bb)[t];
    __half2* o2 = reinterpret_cast<__half2*>(out + (size_t)row * DM);
    o2[2 * t]     = __floats2half2_rn((xv.x - mean) * inv * wv.x + bv.x,
                                      (xv.y - mean) * inv * wv.y + bv.y);
    o2[2 * t + 1] = __floats2half2_rn((xv.z - mean) * inv * wv.z + bv.z,
                                      (xv.w - mean) * inv * wv.w + bv.w);
}

// ---------------- weight transposes (to [N][K], half) -------------------------
__global__ void transpose_kernel(const float* __restrict__ in, __half* __restrict__ out,
                                 int R, int C)
{
    __shared__ float tile[32][33];
    int r0 = blockIdx.y * 32, c0 = blockIdx.x * 32;
    int tx = threadIdx.x, ty = threadIdx.y;
    #pragma unroll
    for (int i = 0; i < 32; i += 8)
        tile[ty + i][tx] = in[(size_t)(r0 + ty + i) * C + c0 + tx];
    __syncthreads();
    #pragma unroll
    for (int i = 0; i < 32; i += 8)
        out[(size_t)(c0 + ty + i) * R + r0 + tx] = __float2half_rn(tile[tx][ty + i]);
}

// QKV: g_wqkv_t[(sel*1024 + n*64 + h)][e] = W_sel[n][e][h]; query scaled by 1/8
__global__ void qkv_t_kernel(const float* __restrict__ Wq, const float* __restrict__ Wk,
                             const float* __restrict__ Wv)
{
    __shared__ float tile[32][33];
    int b   = blockIdx.z;
    int sel = b >> 4, n = b & 15;
    const float* W = (sel == 0) ? Wq : (sel == 1) ? Wk : Wv;
    float scale = (sel == 0) ? 0.125f : 1.0f;
    const float* src = W + (size_t)n * DM * DH;       // [E=1024][H=64]
    int e0 = blockIdx.x * 32, h0 = blockIdx.y * 32;
    int tx = threadIdx.x, ty = threadIdx.y;
    #pragma unroll
    for (int i = 0; i < 32; i += 8)
        tile[ty + i][tx] = src[(size_t)(e0 + ty + i) * DH + h0 + tx];
    __syncthreads();
    #pragma unroll
    for (int i = 0; i < 32; i += 8)
        g_wqkv_t[(size_t)(sel * DM + n * 64 + h0 + ty + i) * DM + e0 + tx] =
            __float2half_rn(tile[tx][ty + i] * scale);
}

__global__ void bias_pack_kernel(const float* __restrict__ Bq, const float* __restrict__ Bk,
                                 const float* __restrict__ Bv)
{
    int idx = blockIdx.x * 256 + threadIdx.x;
    if (idx < 3 * DM) {
        int sel = idx / DM, col = idx % DM;
        const float* Bp = (sel == 0) ? Bq : (sel == 1) ? Bk : Bv;
        g_bqkv[idx] = Bp[col] * (sel == 0 ? 0.125f : 1.0f);
    }
}

// ---------------- pipelined fp16 mma GEMM (ldmatrix gathers) -------------------
// C[M,N] = A[M,K] * Bt[N,K]^T. Block 128x128, 8 warps (4m x 2n), warp 32x64.
// BK=32/stage, 3-stage cp.async. Rows stride 40 halves (A rows 0-127, B rows
// 128-255): ldmatrix banks 20r mod 32, conflict-free.
// mode 0: +bias -> half   1: +bias,GELU -> half   2: +bias,+add(f32) -> f32
#define GSTGB 20480   // bytes per stage: 256 rows * 40 halves * 2

__global__ __launch_bounds__(256) void mgemm(
    const __half* __restrict__ A, const __half* __restrict__ Bt,
    void* __restrict__ Cv, int M, int N, int K,
    const float* __restrict__ bias, const float* __restrict__ add, int mode)
{
    extern __shared__ __align__(16) unsigned char smb[];
    uint32_t sb = smem_u32(smb);
    int t    = threadIdx.x;
    int lane = t & 31, wid = t >> 5;
    int g    = lane >> 2, tig = lane & 3;
    int lr   = lane & 7, quad = lane >> 3;
    int wm   = (wid >> 1) * 32;
    int wn   = (wid & 1) * 64;
    int m0   = blockIdx.y * 128, n0 = blockIdx.x * 128;
    int NC   = K >> 5;

    float acc[2][8][4];
    #pragma unroll
    for (int i = 0; i < 2; i++)
        #pragma unroll
        for (int j = 0; j < 8; j++)
            #pragma unroll
            for (int q = 0; q < 4; q++) acc[i][j][q] = 0.f;

    // cp.async slots: 4 x 16B (8 halves) per thread per stage
    uint32_t so[4];
    const __half* gp[4];
    #pragma unroll
    for (int u = 0; u < 4; u++) {
        int idx = u * 256 + t;
        bool isB = idx >= 512;
        int v = idx & 511;
        int r = v >> 2, w = v & 3;
        so[u] = (uint32_t)(((isB ? 5120 : 0) + r * 40 + w * 8) * 2);
        gp[u] = (isB ? Bt + (size_t)(n0 + r) * K : A + (size_t)(m0 + r) * K) + w * 8;
    }

    #pragma unroll
    for (int c = 0; c < 2; c++) {
        uint32_t base = sb + c * GSTGB;
        #pragma unroll
        for (int u = 0; u < 4; u++) cp_async16(base + so[u], gp[u] + c * 32);
        CP_COMMIT();
    }

    // per-lane ldmatrix base offsets (halves)
    int a_row = lr + (quad & 1) * 8, a_kof = (quad >> 1) * 8;       // A-type frag
    int b_row = lr + (quad >> 1) * 8, b_kof = (quad & 1) * 8;       // B-type frag

    for (int c = 0; c < NC; c++) {
        CP_WAIT(1);
        __syncthreads();
        uint32_t stb = sb + (c % 3) * GSTGB;
        #pragma unroll
        for (int ko = 0; ko < 32; ko += 16) {   // halves
            uint32_t a[2][4];
            #pragma unroll
            for (int i = 0; i < 2; i++)
                ldm_x4(a[i], stb + (uint32_t)(((wm + i * 16 + a_row) * 40 + ko + a_kof) * 2));
            #pragma unroll
            for (int j2 = 0; j2 < 4; j2++) {
                uint32_t bb[4];
                ldm_x4(bb, stb + (uint32_t)(((128 + wn + j2 * 16 + b_row) * 40 + ko + b_kof) * 2));
                mma16816(acc[0][j2 * 2],     a[0], bb[0], bb[1]);
                mma16816(acc[1][j2 * 2],     a[1], bb[0], bb[1]);
                mma16816(acc[0][j2 * 2 + 1], a[0], bb[2], bb[3]);
                mma16816(acc[1][j2 * 2 + 1], a[1], bb[2], bb[3]);
            }
        }
        __syncthreads();
        if (c + 2 < NC) {
            uint32_t base = sb + ((c + 2) % 3) * GSTGB;
            #pragma unroll
            for (int u = 0; u < 4; u++) cp_async16(base + so[u], gp[u] + (c + 2) * 32);
        }
        CP_COMMIT();
    }

    // epilogue
    #pragma unroll
    for (int i = 0; i < 2; i++) {
        int r0 = m0 + wm + i * 16 + g;
        int r1 = r0 + 8;
        #pragma unroll
        for (int j = 0; j < 8; j++) {
            int col = n0 + wn + j * 8 + 2 * tig;
            float b0 = bias[col], b1 = bias[col + 1];
            float v0 = acc[i][j][0] + b0, v1 = acc[i][j][1] + b1;
            float v2 = acc[i][j][2] + b0, v3 = acc[i][j][3] + b1;
            if (mode == 1) {
                v0 = 0.5f * v0 * (1.0f + erff(v0 * 0.70710678118654752f));
                v1 = 0.5f * v1 * (1.0f + erff(v1 * 0.70710678118654752f));
                v2 = 0.5f * v2 * (1.0f + erff(v2 * 0.70710678118654752f));
                v3 = 0.5f * v3 * (1.0f + erff(v3 * 0.70710678118654752f));
            }
            if (mode == 2) {
                float* C = (float*)Cv;
                float2 a0 = *reinterpret_cast<const float2*>(add + (size_t)r0 * N + col);
                float2 a1 = *reinterpret_cast<const float2*>(add + (size_t)r1 * N + col);
                *reinterpret_cast<float2*>(C + (size_t)r0 * N + col) = make_float2(v0 + a0.x, v1 + a0.y);
                *reinterpret_cast<float2*>(C + (size_t)r1 * N + col) = make_float2(v2 + a1.x, v3 + a1.y);
            } else {
                __half* C = (__half*)Cv;
                *reinterpret_cast<__half2*>(C + (size_t)r0 * N + col) = __floats2half2_rn(v0, v1);
                *reinterpret_cast<__half2*>(C + (size_t)r1 * N + col) = __floats2half2_rn(v2, v3);
            }
        }
    }
}

// ---------------- fp16 flash attention (ldmatrix gathers) ----------------------
#define QSTRH 72
#define KVSTRH 72
#define KOFFH(s) (9216 + (s) * 2304)
#define VOFFH(s) (13824 + (s) * 2304)
#define FLASH_SMEM 36864

__global__ __launch_bounds__(256) void flash_mma(const __half* __restrict__ qkv,
                                                 __half* __restrict__ ctx)
{
    extern __shared__ __align__(16) unsigned char smb[];
    uint32_t sb = smem_u32(smb);
    int t    = threadIdx.x;
    int lane = t & 31, wid = t >> 5;
    int g    = lane >> 2, tig = lane & 3;
    int lr   = lane & 7, quad = lane >> 3;
    int n    = blockIdx.y & (NH - 1);
    int b    = blockIdx.y >> 4;
    int q0   = blockIdx.x * 128;
    const __half* base = qkv + (size_t)b * SEQ * (3 * DM);

    // Q tile: 128 rows x 64 halves
    #pragma unroll
    for (int u = 0; u < 4; u++) {
        int idx = u * 256 + t;
        int r = idx >> 3, w = idx & 7;
        cp_async16(sb + (uint32_t)((r * QSTRH + w * 8) * 2),
                   base + (size_t)(q0 + r) * (3 * DM) + n * 64 + w * 8);
    }
    CP_COMMIT();
    // KV stages 0,1: t<128 K, t>=128 V
    {
        int tt = t & 127;
        #pragma unroll
        for (int s = 0; s < 2; s++) {
            #pragma unroll
            for (int u = 0; u < 2; u++) {
                int idx = u * 128 + tt;
                int r = idx >> 3, w = idx & 7;
                const __half* gsrc = base + (size_t)(s * 32 + r) * (3 * DM) + n * 64 + w * 8;
                if (t < 128)
                    cp_async16(sb + (uint32_t)((KOFFH(s) + r * KVSTRH + w * 8) * 2), gsrc + DM);
                else
                    cp_async16(sb + (uint32_t)((VOFFH(s) + r * KVSTRH + w * 8) * 2), gsrc + 2 * DM);
            }
            CP_COMMIT();
        }
    }
    CP_WAIT(2);
    __syncthreads();

    int a_row = lr + (quad & 1) * 8, a_kof = (quad >> 1) * 8;   // A-type frag
    int b_row = lr + (quad >> 1) * 8, b_kof = (quad & 1) * 8;   // B-type frag

    // preload Q frags (pre-scaled 1/8 at projection); Q region becomes P after
    uint32_t qa[4][4];
    #pragma unroll
    for (int ks = 0; ks < 4; ks++)
        ldm_x4(qa[ks], sb + (uint32_t)(((16 * wid + a_row) * QSTRH + ks * 16 + a_kof) * 2));
    uint32_t* Pu = reinterpret_cast<uint32_t*>(smb);   // overlay, stride 20 u32
    int qr = 16 * wid + g;

    float o[8][4];
    #pragma unroll
    for (int j = 0; j < 8; j++)
        #pragma unroll
        for (int q = 0; q < 4; q++) o[j][q] = 0.f;
    float m0r = -INFINITY, m1r = -INFINITY, l0 = 0.f, l1 = 0.f;

    int qg0 = q0 + 16 * wid + g;
    int qg1 = qg0 + 8;

    for (int c = 0; c < SEQ / 32; c++) {     // EPS-mask quirk: ALL tiles
        CP_WAIT(1);
        __syncthreads();
        uint32_t kbase = sb + (uint32_t)(KOFFH(c & 1) * 2);
        uint32_t vbase = sb + (uint32_t)(VOFFH(c & 1) * 2);

        // S = Q K^T : 4 k16-steps x 2 ldmatrix.x4 (4 n-groups)
        float sc[4][4];
        #pragma unroll
        for (int j = 0; j < 4; j++)
            #pragma unroll
            for (int q = 0; q < 4; q++) sc[j][q] = 0.f;
        #pragma unroll
        for (int ks = 0; ks < 4; ks++)
            #pragma unroll
            for (int j2 = 0; j2 < 2; j2++) {
                uint32_t bb[4];
                ldm_x4(bb, kbase + (uint32_t)(((j2 * 16 + b_row) * KVSTRH + ks * 16 + b_kof) * 2));
                mma16816(sc[j2 * 2],     qa[ks], bb[0], bb[1]);
                mma16816(sc[j2 * 2 + 1], qa[ks], bb[2], bb[3]);
            }

        // mask + online softmax
        int k0 = c * 32;
        float mt0 = -INFINITY, mt1 = -INFINITY;
        #pragma unroll
        for (int j = 0; j < 4; j++) {
            int kc = k0 + j * 8 + 2 * tig;
            if (qg0 < kc)     sc[j][0] = 1e-10f;
            if (qg0 < kc + 1) sc[j][1] = 1e-10f;
            if (qg1 < kc)     sc[j][2] = 1e-10f;
            if (qg1 < kc + 1) sc[j][3] = 1e-10f;
            mt0 = fmaxf(mt0, fmaxf(sc[j][0], sc[j][1]));
            mt1 = fmaxf(mt1, fmaxf(sc[j][2], sc[j][3]));
        }
        #pragma unroll
        for (int msk = 1; msk < 4; msk <<= 1) {
            mt0 = fmaxf(mt0, __shfl_xor_sync(0xffffffffu, mt0, msk));
            mt1 = fmaxf(mt1, __shfl_xor_sync(0xffffffffu, mt1, msk));
        }
        float mn0 = fmaxf(m0r, mt0), mn1 = fmaxf(m1r, mt1);
        float lt0 = 0.f, lt1 = 0.f;
        #pragma unroll
        for (int j = 0; j < 4; j++) {
            sc[j][0] = __expf(sc[j][0] - mn0);
            sc[j][1] = __expf(sc[j][1] - mn0);
            sc[j][2] = __expf(sc[j][2] - mn1);
            sc[j][3] = __expf(sc[j][3] - mn1);
            lt0 += sc[j][0] + sc[j][1];
            lt1 += sc[j][2] + sc[j][3];
        }
        #pragma unroll
        for (int msk = 1; msk < 4; msk <<= 1) {
            lt0 += __shfl_xor_sync(0xffffffffu, lt0, msk);
            lt1 += __shfl_xor_sync(0xffffffffu, lt1, msk);
        }
        float c0 = __expf(m0r - mn0), c1 = __expf(m1r - mn1);
        l0 = l0 * c0 + lt0;  l1 = l1 * c1 + lt1;
        m0r = mn0;  m1r = mn1;
        #pragma unroll
        for (int j = 0; j < 8; j++) {
            o[j][0] *= c0; o[j][1] *= c0;
            o[j][2] *= c1; o[j][3] *= c1;
        }

        // P -> smem as half2 pairs
        #pragma unroll
        for (int j = 0; j < 4; j++) {
            __half2 p01 = __floats2half2_rn(sc[j][0], sc[j][1]);
            __half2 p23 = __floats2half2_rn(sc[j][2], sc[j][3]);
            Pu[qr * 20 + j * 4 + tig]       = *reinterpret_cast<uint32_t*>(&p01);
            Pu[(qr + 8) * 20 + j * 4 + tig] = *reinterpret_cast<uint32_t*>(&p23);
        }
        __syncwarp();

        // O += P V : P frags via ldmatrix.x4, V^T via ldmatrix.x4.trans
        #pragma unroll
        for (int ks = 0; ks < 2; ks++) {
            uint32_t pa[4];
            ldm_x4(pa, sb + (uint32_t)(((16 * wid + a_row) * 40 + ks * 16 + a_kof) * 2));
            #pragma unroll
            for (int cb = 0; cb < 4; cb++) {
                int row = ks * 16 + lr + (quad & 1) * 8;
                int col = cb * 16 + (quad >> 1) * 8;
                uint32_t vv[4];
                ldm_x4_trans(vv, vbase + (uint32_t)((row * KVSTRH + col) * 2));
                mma16816(o[cb * 2],     pa, vv[0], vv[1]);
                mma16816(o[cb * 2 + 1], pa, vv[2], vv[3]);
            }
        }
        __syncthreads();

        // prefetch KV stage c+2 into buffer c&1
        if (c + 2 < SEQ / 32) {
            int tt = t & 127;
            #pragma unroll
            for (int u = 0; u < 2; u++) {
                int idx = u * 128 + tt;
                int r = idx >> 3, w = idx & 7;
                const __half* gsrc = base + (size_t)((c + 2) * 32 + r) * (3 * DM) + n * 64 + w * 8;
                if (t < 128)
                    cp_async16(sb + (uint32_t)((KOFFH(c & 1) + r * KVSTRH + w * 8) * 2), gsrc + DM);
                else
                    cp_async16(sb + (uint32_t)((VOFFH(c & 1) + r * KVSTRH + w * 8) * 2), gsrc + 2 * DM);
            }
        }
        CP_COMMIT();
    }

    // writeback (half: feeds attn-out GEMM A operand)
    float inv0 = 1.0f / l0, inv1 = 1.0f / l1;
    size_t r0 = (size_t)(b * SEQ + q0 + 16 * wid + g) * DM;
    size_t r1 = r0 + 8 * DM;
    #pragma unroll
    for (int hj = 0; hj < 8; hj++) {
        int col = n * 64 + hj * 8 + 2 * tig;
        *reinterpret_cast<__half2*>(ctx + r0 + col) =
            __floats2half2_rn(o[hj][0] * inv0, o[hj][1] * inv0);
        *reinterpret_cast<__half2*>(ctx + r1 + col) =
            __floats2half2_rn(o[hj][2] * inv1, o[hj][3] * inv1);
    }
}

// ---------------- launch -----------------------------------------------------
extern "C" void kernel_launch(void* const* d_in, const int* in_sizes, int n_in,
                              void* d_out, int out_size)
{
    const float* residual   = (const float*)d_in[0];
    const float* W_key      = (const float*)d_in[1];
    const float* W_query    = (const float*)d_in[2];
    const float* W_values   = (const float*)d_in[3];
    const float* W_attn_out = (const float*)d_in[4];
    const float* B_key      = (const float*)d_in[5];
    const float* B_query    = (const float*)d_in[6];
    const float* B_values   = (const float*)d_in[7];
    const float* B_attn_out = (const float*)d_in[8];
    const float* ln1_w      = (const float*)d_in[9];
    const float* ln1_b      = (const float*)d_in[10];
    const float* ln2_w      = (const float*)d_in[11];
    const float* ln2_b      = (const float*)d_in[12];
    const float* W_mlp_in   = (const float*)d_in[13];
    const float* W_mlp_out  = (const float*)d_in[14];
    const float* B_mlp_in   = (const float*)d_in[15];
    const float* B_mlp_out  = (const float*)d_in[16];
    float* out = (float*)d_out;

    __half *xln, *qkvp, *ctxp, *yp, *hp, *wqkvt, *watt, *wmin, *wmout;
    float *midp, *bqkvp;
    cudaGetSymbolAddress((void**)&xln,   g_xln);
    cudaGetSymbolAddress((void**)&qkvp,  g_qkv);
    cudaGetSymbolAddress((void**)&ctxp,  g_ctx);
    cudaGetSymbolAddress((void**)&midp,  g_mid);
    cudaGetSymbolAddress((void**)&yp,    g_y);
    cudaGetSymbolAddress((void**)&hp,    g_h);
    cudaGetSymbolAddress((void**)&wqkvt, g_wqkv_t);
    cudaGetSymbolAddress((void**)&watt,  g_watt_t);
    cudaGetSymbolAddress((void**)&wmin,  g_wmin_t);
    cudaGetSymbolAddress((void**)&wmout, g_wmout_t);
    cudaGetSymbolAddress((void**)&bqkvp, g_bqkv);

    const int GS = 3 * GSTGB;   // 61440 B
    cudaFuncSetAttribute(mgemm,     cudaFuncAttributeMaxDynamicSharedMemorySize, GS);
    cudaFuncSetAttribute(flash_mma, cudaFuncAttributeMaxDynamicSharedMemorySize, FLASH_SMEM);

    dim3 t32x8(32, 8);

    // weight prep (deterministic every call)
    qkv_t_kernel<<<dim3(DM / 32, DH / 32, 48), t32x8>>>(W_query, W_key, W_values);
    bias_pack_kernel<<<12, 256>>>(B_query, B_key, B_values);
    transpose_kernel<<<dim3(DM / 32, DM / 32),  t32x8>>>(W_attn_out, watt, DM, DM);
    transpose_kernel<<<dim3(DMLP / 32, DM / 32), t32x8>>>(W_mlp_in,  wmin, DM, DMLP);
    transpose_kernel<<<dim3(DM / 32, DMLP / 32), t32x8>>>(W_mlp_out, wmout, DMLP, DM);

    // 1. LN1
    ln_kernel<<<MROWS, 256>>>(residual, ln1_w, ln1_b, xln);
    // 2. QKV projection [4096,1024]x[1024,3072]
    mgemm<<<dim3(3 * DM / 128, MROWS / 128), 256, GS>>>(
        xln, wqkvt, qkvp, MROWS, 3 * DM, DM, bqkvp, nullptr, 0);
    // 3. attention (EPS-masked full softmax, fp16 tensor cores)
    flash_mma<<<dim3(SEQ / 128, BATCH * NH), 256, FLASH_SMEM>>>(qkvp, ctxp);
    // 4. attn out projection + residual -> mid (fp32)
    mgemm<<<dim3(DM / 128, MROWS / 128), 256, GS>>>(
        ctxp, watt, midp, MROWS, DM, DM, B_attn_out, residual, 2);
    // 5. LN2
    ln_kernel<<<MROWS, 256>>>(midp, ln2_w, ln2_b, yp);
    // 6. MLP in + exact GELU
    mgemm<<<dim3(DMLP / 128, MROWS / 128), 256, GS>>>(
        yp, wmin, hp, MROWS, DMLP, DM, B_mlp_in, nullptr, 1);
    // 7. MLP out + residual -> output (fp32)
    mgemm<<<dim3(DM / 128, MROWS / 128), 256, GS>>>(
        hp, wmout, out, MROWS, DM, DMLP, B_mlp_out, midp, 2);
}